// round 1
// baseline (speedup 1.0000x reference)
#include <cuda_runtime.h>

#define B_   8
#define N_   1024
#define M_   24576      // B_*3*N_
#define C2   256
#define H3   128
#define KNN_ 20
#define EPSF 1e-6f

// ---------------- scratch (allocation-free: __device__ globals) ----------------
__device__ float g_pc[B_*N_*3];     // centered points
__device__ float g_m [B_*N_*3];     // mean of 20-NN per point
__device__ float g_X0[C2*M_];
__device__ float g_X1[C2*M_];
__device__ float g_D [C2*M_];
__device__ float g_Nt[H3*M_];
__device__ float g_D1[H3*M_];
__device__ float g_DX[H3*M_];
__device__ float g_net[H3*24];      // pooled features: [c][b*3+v]

// ---------------- 1. center per cloud ----------------
__global__ void center_kernel(const float* __restrict__ p) {
    int b = blockIdx.x;
    __shared__ float s[3][256];
    float s0 = 0.f, s1 = 0.f, s2 = 0.f;
    for (int n = threadIdx.x; n < N_; n += 256) {
        const float* q = p + (size_t)(b*N_ + n)*3;
        s0 += q[0]; s1 += q[1]; s2 += q[2];
    }
    s[0][threadIdx.x] = s0; s[1][threadIdx.x] = s1; s[2][threadIdx.x] = s2;
    __syncthreads();
    for (int st = 128; st > 0; st >>= 1) {
        if (threadIdx.x < st) {
            s[0][threadIdx.x] += s[0][threadIdx.x + st];
            s[1][threadIdx.x] += s[1][threadIdx.x + st];
            s[2][threadIdx.x] += s[2][threadIdx.x + st];
        }
        __syncthreads();
    }
    float m0 = s[0][0] / N_, m1 = s[1][0] / N_, m2 = s[2][0] / N_;
    for (int n = threadIdx.x; n < N_; n += 256) {
        const float* q = p + (size_t)(b*N_ + n)*3;
        float* o = g_pc + (size_t)(b*N_ + n)*3;
        o[0] = q[0] - m0; o[1] = q[1] - m1; o[2] = q[2] - m2;
    }
}

// ---------------- 2. KNN (k=20, self included) -> mean of neighbor coords ----------------
__global__ void knn_mean_kernel() {
    int b     = blockIdx.x >> 2;
    int chunk = blockIdx.x & 3;
    __shared__ float sp[N_*3];
    __shared__ float sxx[N_];
    for (int t = threadIdx.x; t < N_*3; t += 256) sp[t] = g_pc[b*N_*3 + t];
    __syncthreads();
    for (int t = threadIdx.x; t < N_; t += 256) {
        float x = sp[t*3], y = sp[t*3+1], z = sp[t*3+2];
        sxx[t] = x*x + y*y + z*z;
    }
    __syncthreads();

    int i = chunk*256 + threadIdx.x;
    float xi = sp[i*3], yi = sp[i*3+1], zi = sp[i*3+2];
    float xxi = sxx[i];

    float bd[KNN_]; int bi[KNN_];
#pragma unroll
    for (int t = 0; t < KNN_; t++) { bd[t] = -3.4e38f; bi[t] = 0; }

    for (int j = 0; j < N_; j++) {
        float dot = xi*sp[j*3] + yi*sp[j*3+1] + zi*sp[j*3+2];
        float nd  = 2.f*dot - xxi - sxx[j];         // == -xx_i - (-2 dot) - xx_j
        if (nd > bd[KNN_-1]) {                      // strict > => ties keep lower index
            int t = KNN_-1;
            while (t > 0 && bd[t-1] < nd) { bd[t] = bd[t-1]; bi[t] = bi[t-1]; t--; }
            bd[t] = nd; bi[t] = j;
        }
    }
    float m0 = 0.f, m1 = 0.f, m2 = 0.f;
#pragma unroll
    for (int t = 0; t < KNN_; t++) {
        int j = bi[t];
        m0 += sp[j*3]; m1 += sp[j*3+1]; m2 += sp[j*3+2];
    }
    float* o = g_m + (size_t)(b*N_ + i)*3;
    o[0] = m0 / KNN_; o[1] = m1 / KNN_; o[2] = m2 / KNN_;
}

// ---------------- 3. fused edge-feature + W_pos + pool_k ----------------
// X0[o, (b*3+v)*N + n] = Wpos[o,0]*(m-p)_v + Wpos[o,1]*p_v + Wpos[o,2]*(m x p)_v
__global__ void featpos_kernel(const float* __restrict__ Wpos) {
    int bk = blockIdx.x;                 // 0..191 = b(8) * v(3) * chunk(8)
    int b = bk / 24; int rem = bk % 24;
    int v = rem / 8; int chunk = rem % 8;
    int n0 = chunk * 128;
    __shared__ float f0[128], f1[128], f2[128];
    if (threadIdx.x < 128) {
        int n = n0 + threadIdx.x;
        const float* pp = g_pc + (size_t)(b*N_ + n)*3;
        const float* mm = g_m  + (size_t)(b*N_ + n)*3;
        float p0 = pp[0], p1 = pp[1], p2 = pp[2];
        float m0 = mm[0], m1 = mm[1], m2 = mm[2];
        float pv = (v == 0) ? p0 : ((v == 1) ? p1 : p2);
        float mv = (v == 0) ? m0 : ((v == 1) ? m1 : m2);
        float cv;                                   // (m x p)_v
        if (v == 0)      cv = m1*p2 - m2*p1;
        else if (v == 1) cv = m2*p0 - m0*p2;
        else             cv = m0*p1 - m1*p0;
        f0[threadIdx.x] = mv - pv;
        f1[threadIdx.x] = pv;
        f2[threadIdx.x] = cv;
    }
    __syncthreads();
    int nl = threadIdx.x & 127;
    int oo = threadIdx.x >> 7;
    size_t colbase = (size_t)(b*3 + v)*N_ + n0;
    for (int ob = 0; ob < C2; ob += 2) {
        int o = ob + oo;
        float w0 = Wpos[o*3], w1 = Wpos[o*3+1], w2 = Wpos[o*3+2];
        g_X0[(size_t)o*M_ + colbase + nl] = w0*f0[nl] + w1*f1[nl] + w2*f2[nl];
    }
}

// ---------------- 4. SGEMM: Y[O,M_] = W[O,C] @ X[C,M_] (+ Add) ----------------
__global__ __launch_bounds__(256, 2)
void sgemm_kernel(const float* __restrict__ A, const float* __restrict__ Bm,
                  float* __restrict__ Y, const float* __restrict__ Add, int C) {
    __shared__ float As[8][128];
    __shared__ float Bs[8][128];
    int tid = threadIdx.x;
    int nBase = blockIdx.x * 128;
    int oBase = blockIdx.y * 128;
    int aRow = tid >> 1;
    int aCol = (tid & 1) * 4;
    int bRow = tid >> 5;
    int bCol = (tid & 31) * 4;
    int ty = tid >> 4, tx = tid & 15;
    float acc[8][8];
#pragma unroll
    for (int i = 0; i < 8; i++)
#pragma unroll
        for (int j = 0; j < 8; j++) acc[i][j] = 0.f;

    for (int k0 = 0; k0 < C; k0 += 8) {
        float4 av = *(const float4*)&A[(size_t)(oBase + aRow)*C + k0 + aCol];
        As[aCol+0][aRow] = av.x; As[aCol+1][aRow] = av.y;
        As[aCol+2][aRow] = av.z; As[aCol+3][aRow] = av.w;
        float4 bv = *(const float4*)&Bm[(size_t)(k0 + bRow)*M_ + nBase + bCol];
        *(float4*)&Bs[bRow][bCol] = bv;
        __syncthreads();
#pragma unroll
        for (int k = 0; k < 8; k++) {
            float4 a0 = *(float4*)&As[k][ty*8];
            float4 a1 = *(float4*)&As[k][ty*8 + 4];
            float4 b0 = *(float4*)&Bs[k][tx*8];
            float4 b1 = *(float4*)&Bs[k][tx*8 + 4];
            float ar[8] = {a0.x, a0.y, a0.z, a0.w, a1.x, a1.y, a1.z, a1.w};
            float br[8] = {b0.x, b0.y, b0.z, b0.w, b1.x, b1.y, b1.z, b1.w};
#pragma unroll
            for (int i = 0; i < 8; i++)
#pragma unroll
                for (int j = 0; j < 8; j++) acc[i][j] += ar[i] * br[j];
        }
        __syncthreads();
    }

#pragma unroll
    for (int i = 0; i < 8; i++) {
        size_t rb = (size_t)(oBase + ty*8 + i)*M_ + nBase + tx*8;
        if (Add != nullptr) {
#pragma unroll
            for (int j = 0; j < 8; j += 4) {
                float4 ad = *(const float4*)&Add[rb + j];
                float4 r = make_float4(acc[i][j]   + ad.x, acc[i][j+1] + ad.y,
                                       acc[i][j+2] + ad.z, acc[i][j+3] + ad.w);
                *(float4*)&Y[rb + j] = r;
            }
        } else {
#pragma unroll
            for (int j = 0; j < 8; j += 4) {
                float4 r = make_float4(acc[i][j], acc[i][j+1], acc[i][j+2], acc[i][j+3]);
                *(float4*)&Y[rb + j] = r;
            }
        }
    }
}

// ---------------- 5. VN leaky-relu (slope 0), in place over D ----------------
__global__ void lrelu_kernel(const float* __restrict__ X, float* __restrict__ D) {
    int idx = blockIdx.x * 256 + threadIdx.x;    // over C*B_*N_
    int c = idx >> 13;           // / 8192
    int r = idx & 8191;
    int b = r >> 10, n = r & 1023;
    size_t base = (size_t)c*M_ + (size_t)b*3*N_ + n;
    float x0 = X[base], x1 = X[base + N_], x2 = X[base + 2*N_];
    float d0 = D[base], d1 = D[base + N_], d2 = D[base + 2*N_];
    float dot = x0*d0 + x1*d1 + x2*d2;
    if (dot < 0.f) {
        float dd = d0*d0 + d1*d1 + d2*d2;
        float s = dot / (dd + EPSF);
        D[base]        = x0 - s*d0;
        D[base + N_]   = x1 - s*d1;
        D[base + 2*N_] = x2 - s*d2;
    } else {
        D[base] = x0; D[base + N_] = x1; D[base + 2*N_] = x2;
    }
}

// ---------------- 6. mean over points -> broadcast concat (rows 128..255) ----------------
__global__ void pool_concat_kernel(float* __restrict__ Xn) {
    int w    = blockIdx.x * 8 + (threadIdx.x >> 5);  // 0..3071
    int lane = threadIdx.x & 31;
    int c = w / 24; int rem = w % 24;
    size_t base = (size_t)c*M_ + (size_t)rem*N_;
    float s = 0.f;
#pragma unroll
    for (int t = 0; t < 32; t++) s += Xn[base + lane + t*32];
#pragma unroll
    for (int off = 16; off; off >>= 1) s += __shfl_xor_sync(0xffffffffu, s, off);
    float mean = s * (1.f / N_);
    size_t ob = (size_t)(c + H3)*M_ + (size_t)rem*N_;
#pragma unroll
    for (int t = 0; t < 32; t++) Xn[ob + lane + t*32] = mean;
}

// ---------------- 7. final mean over points -> g_net ----------------
__global__ void final_pool_kernel(const float* __restrict__ Xn) {
    int w    = blockIdx.x * 8 + (threadIdx.x >> 5);
    int lane = threadIdx.x & 31;
    int c = w / 24; int rem = w % 24;
    size_t base = (size_t)c*M_ + (size_t)rem*N_;
    float s = 0.f;
#pragma unroll
    for (int t = 0; t < 32; t++) s += Xn[base + lane + t*32];
#pragma unroll
    for (int off = 16; off; off >>= 1) s += __shfl_xor_sync(0xffffffffu, s, off);
    if (lane == 0) g_net[c*24 + rem] = s * (1.f / N_);
}

// ---------------- 8. head: lrelu(Wd_act) + W_c ----------------
__global__ void final_kernel(const float* __restrict__ Wd, const float* __restrict__ Wc,
                             float* __restrict__ out) {
    __shared__ float s_net[H3*24];
    __shared__ float s_act[H3*24];
    int o = threadIdx.x;                     // 0..127
    for (int t = o; t < H3*24; t += 128) s_net[t] = g_net[t];
    __syncthreads();

    float dcol[24];
#pragma unroll
    for (int col = 0; col < 24; col++) dcol[col] = 0.f;
    for (int i = 0; i < H3; i++) {
        float w = Wd[o*H3 + i];
#pragma unroll
        for (int col = 0; col < 24; col++) dcol[col] += w * s_net[i*24 + col];
    }
#pragma unroll
    for (int b = 0; b < 8; b++) {
        float x0 = s_net[o*24 + b*3], x1 = s_net[o*24 + b*3 + 1], x2 = s_net[o*24 + b*3 + 2];
        float d0 = dcol[b*3], d1 = dcol[b*3 + 1], d2 = dcol[b*3 + 2];
        float dot = x0*d0 + x1*d1 + x2*d2;
        float a0 = x0, a1 = x1, a2 = x2;
        if (dot < 0.f) {
            float dd = d0*d0 + d1*d1 + d2*d2;
            float s = dot / (dd + EPSF);
            a0 = x0 - s*d0; a1 = x1 - s*d1; a2 = x2 - s*d2;
        }
        s_act[o*24 + b*3] = a0; s_act[o*24 + b*3 + 1] = a1; s_act[o*24 + b*3 + 2] = a2;
    }
    __syncthreads();

    float oc[24];
#pragma unroll
    for (int col = 0; col < 24; col++) oc[col] = 0.f;
    for (int i = 0; i < H3; i++) {
        float w = Wc[o*H3 + i];
#pragma unroll
        for (int col = 0; col < 24; col++) oc[col] += w * s_act[i*24 + col];
    }
#pragma unroll
    for (int col = 0; col < 24; col++) {
        int b = col / 3, v = col % 3;
        out[b*384 + o*3 + v] = oc[col];      // c.reshape(B,-1): index o*3+v
    }
}

// ---------------- host ----------------
static float* symaddr(const void* sym) {
    void* p = nullptr;
    cudaGetSymbolAddress(&p, sym);
    return (float*)p;
}

extern "C" void kernel_launch(void* const* d_in, const int* in_sizes, int n_in,
                              void* d_out, int out_size) {
    const float* p      = (const float*)d_in[0];
    const float* Wpos   = (const float*)d_in[1];
    const float* Wd0s   = (const float*)d_in[2];
    const float* W0s    = (const float*)d_in[3];
    const float* Wd1s   = (const float*)d_in[4];
    const float* W1s    = (const float*)d_in[5];
    const float* Wss    = (const float*)d_in[6];
    const float* Wd_act = (const float*)d_in[7];
    const float* Wc     = (const float*)d_in[8];
    float* out = (float*)d_out;

    float* X  = symaddr(g_X0);
    float* Xn = symaddr(g_X1);
    float* D  = symaddr(g_D);
    float* Nt = symaddr(g_Nt);
    float* D1 = symaddr(g_D1);
    float* DX = symaddr(g_DX);

    center_kernel<<<B_, 256>>>(p);
    knn_mean_kernel<<<B_*4, 256>>>();
    featpos_kernel<<<B_*3*8, 256>>>(Wpos);

    for (int i = 0; i < 5; i++) {
        const float* Wd0 = Wd0s + (size_t)i*C2*C2;
        const float* W0  = W0s  + (size_t)i*H3*C2;
        const float* Wd1 = Wd1s + (size_t)i*H3*H3;
        const float* W1  = W1s  + (size_t)i*H3*H3;
        const float* Ws  = Wss  + (size_t)i*H3*C2;

        sgemm_kernel<<<dim3(192, 2), 256>>>(Wd0, X, D, nullptr, C2);   // D = Wd0 @ X
        lrelu_kernel<<<(C2*8192)/256, 256>>>(X, D);                    // D = lrelu(X, D)
        sgemm_kernel<<<dim3(192, 1), 256>>>(W0, D, Nt, nullptr, C2);   // Nt = W0 @ D
        sgemm_kernel<<<dim3(192, 1), 256>>>(Wd1, Nt, D1, nullptr, H3); // D1 = Wd1 @ Nt
        lrelu_kernel<<<(H3*8192)/256, 256>>>(Nt, D1);                  // D1 = lrelu(Nt, D1)
        sgemm_kernel<<<dim3(192, 1), 256>>>(W1, D1, DX, nullptr, H3);  // DX = W1 @ D1
        sgemm_kernel<<<dim3(192, 1), 256>>>(Ws, X, Xn, DX, C2);        // Xn[0:128] = Ws@X + DX
        if (i < 4) {
            pool_concat_kernel<<<384, 256>>>(Xn);                      // Xn[128:256] = mean_n
            float* t = X; X = Xn; Xn = t;
        }
    }

    final_pool_kernel<<<384, 256>>>(Xn);
    final_kernel<<<1, 128>>>(Wd_act, Wc, out);
}

// round 2
// speedup vs baseline: 1.1420x; 1.1420x over previous
#include <cuda_runtime.h>

#define B_   8
#define N_   1024
#define M_   24576      // B_*3*N_
#define C2   256
#define H3   128
#define KNN_ 20
#define EPSF 1e-6f

// ---------------- scratch (allocation-free: __device__ globals) ----------------
__device__ float g_pc[B_*N_*3];       // centered points
__device__ float g_m [B_*N_*3];       // mean of 20-NN per point
__device__ float g_X0[C2*M_];         // pos features (256 rows); rows 0..127 reused as netX
__device__ float g_DS[384*M_];        // GEMM1 output: rows 0..255 = D, 256..383 = S = Ws@X
__device__ float g_Nt[H3*M_];
__device__ float g_D1[H3*M_];
__device__ float g_P [H3*24];         // pooled per (c, b*3+v)
__device__ float g_Wcat[5*384*C2];    // [Wd0; Ws] per block
__device__ float g_Badd[384*24];      // [Wd0;Ws][:,128:] @ P

// ---------------- 1. center per cloud ----------------
__global__ void center_kernel(const float* __restrict__ p) {
    int b = blockIdx.x;
    __shared__ float s[3][256];
    float s0 = 0.f, s1 = 0.f, s2 = 0.f;
    for (int n = threadIdx.x; n < N_; n += 256) {
        const float* q = p + (size_t)(b*N_ + n)*3;
        s0 += q[0]; s1 += q[1]; s2 += q[2];
    }
    s[0][threadIdx.x] = s0; s[1][threadIdx.x] = s1; s[2][threadIdx.x] = s2;
    __syncthreads();
    for (int st = 128; st > 0; st >>= 1) {
        if (threadIdx.x < st) {
            s[0][threadIdx.x] += s[0][threadIdx.x + st];
            s[1][threadIdx.x] += s[1][threadIdx.x + st];
            s[2][threadIdx.x] += s[2][threadIdx.x + st];
        }
        __syncthreads();
    }
    float m0 = s[0][0] / N_, m1 = s[1][0] / N_, m2 = s[2][0] / N_;
    for (int n = threadIdx.x; n < N_; n += 256) {
        const float* q = p + (size_t)(b*N_ + n)*3;
        float* o = g_pc + (size_t)(b*N_ + n)*3;
        o[0] = q[0] - m0; o[1] = q[1] - m1; o[2] = q[2] - m2;
    }
}

// ---------------- 2. KNN (k=20, self included) -> mean of neighbor coords ----------------
__global__ void knn_mean_kernel() {
    int b     = blockIdx.x >> 2;
    int chunk = blockIdx.x & 3;
    __shared__ float sp[N_*3];
    __shared__ float sxx[N_];
    for (int t = threadIdx.x; t < N_*3; t += 256) sp[t] = g_pc[b*N_*3 + t];
    __syncthreads();
    for (int t = threadIdx.x; t < N_; t += 256) {
        float x = sp[t*3], y = sp[t*3+1], z = sp[t*3+2];
        sxx[t] = x*x + y*y + z*z;
    }
    __syncthreads();

    int i = chunk*256 + threadIdx.x;
    float xi = sp[i*3], yi = sp[i*3+1], zi = sp[i*3+2];
    float xxi = sxx[i];

    float bd[KNN_]; int bi[KNN_];
#pragma unroll
    for (int t = 0; t < KNN_; t++) { bd[t] = -3.4e38f; bi[t] = 0; }

    for (int j = 0; j < N_; j++) {
        float dot = xi*sp[j*3] + yi*sp[j*3+1] + zi*sp[j*3+2];
        float nd  = 2.f*dot - xxi - sxx[j];
        if (nd > bd[KNN_-1]) {                      // strict > => ties keep lower index
            int t = KNN_-1;
            while (t > 0 && bd[t-1] < nd) { bd[t] = bd[t-1]; bi[t] = bi[t-1]; t--; }
            bd[t] = nd; bi[t] = j;
        }
    }
    float m0 = 0.f, m1 = 0.f, m2 = 0.f;
#pragma unroll
    for (int t = 0; t < KNN_; t++) {
        int j = bi[t];
        m0 += sp[j*3]; m1 += sp[j*3+1]; m2 += sp[j*3+2];
    }
    float* o = g_m + (size_t)(b*N_ + i)*3;
    o[0] = m0 / KNN_; o[1] = m1 / KNN_; o[2] = m2 / KNN_;
}

// ---------------- 3. fused edge-feature + W_pos + pool_k -> g_X0 ----------------
__global__ void featpos_kernel(const float* __restrict__ Wpos) {
    int bk = blockIdx.x;                 // 0..191 = b(8) * v(3) * chunk(8)
    int b = bk / 24; int rem = bk % 24;
    int v = rem / 8; int chunk = rem % 8;
    int n0 = chunk * 128;
    __shared__ float f0[128], f1[128], f2[128];
    if (threadIdx.x < 128) {
        int n = n0 + threadIdx.x;
        const float* pp = g_pc + (size_t)(b*N_ + n)*3;
        const float* mm = g_m  + (size_t)(b*N_ + n)*3;
        float p0 = pp[0], p1 = pp[1], p2 = pp[2];
        float m0 = mm[0], m1 = mm[1], m2 = mm[2];
        float pv = (v == 0) ? p0 : ((v == 1) ? p1 : p2);
        float mv = (v == 0) ? m0 : ((v == 1) ? m1 : m2);
        float cv;                                   // (m x p)_v
        if (v == 0)      cv = m1*p2 - m2*p1;
        else if (v == 1) cv = m2*p0 - m0*p2;
        else             cv = m0*p1 - m1*p0;
        f0[threadIdx.x] = mv - pv;
        f1[threadIdx.x] = pv;
        f2[threadIdx.x] = cv;
    }
    __syncthreads();
    int nl = threadIdx.x & 127;
    int oo = threadIdx.x >> 7;
    size_t colbase = (size_t)(b*3 + v)*N_ + n0;
    for (int ob = 0; ob < C2; ob += 2) {
        int o = ob + oo;
        float w0 = Wpos[o*3], w1 = Wpos[o*3+1], w2 = Wpos[o*3+2];
        g_X0[(size_t)o*M_ + colbase + nl] = w0*f0[nl] + w1*f1[nl] + w2*f2[nl];
    }
}

// ---------------- 3b. build concatenated [Wd0; Ws] weights ----------------
__global__ void wcat_kernel(const float* __restrict__ Wd0s, const float* __restrict__ Wss) {
    int idx = blockIdx.x * 256 + threadIdx.x;   // 5*384*256
    int i   = idx / (384*C2);
    int rem = idx % (384*C2);
    int r = rem / C2, c = rem % C2;
    float v = (r < C2) ? Wd0s[(size_t)i*C2*C2 + r*C2 + c]
                       : Wss [(size_t)i*H3*C2 + (r - C2)*C2 + c];
    g_Wcat[idx] = v;
}

// ---------------- 3c. Badd[384][24] = Wcat[:,128:] @ P ----------------
__global__ void badd_kernel(const float* __restrict__ Wcat) {
    int idx = blockIdx.x * 256 + threadIdx.x;   // 384*24 = 9216
    if (idx >= 384*24) return;
    int r = idx / 24, cg = idx % 24;
    float s = 0.f;
#pragma unroll 8
    for (int k = 0; k < H3; k++)
        s += Wcat[r*C2 + H3 + k] * g_P[k*24 + cg];
    g_Badd[idx] = s;
}

// ---------------- 4a. SGEMM 128x128: Y = A[.,lda] @ B[K,M_]  (+ Badd per colgroup) ----------------
__global__ __launch_bounds__(256, 2)
void sgemm128(const float* __restrict__ A, int lda, const float* __restrict__ Bm,
              float* __restrict__ Y, int K, const float* __restrict__ Badd) {
    __shared__ float As[8][128];
    __shared__ float Bs[8][128];
    int tid = threadIdx.x;
    int nBase = blockIdx.x * 128;
    int oBase = blockIdx.y * 128;
    int aRow = tid >> 1;
    int aCol = (tid & 1) * 4;
    int bRow = tid >> 5;
    int bCol = (tid & 31) * 4;
    int ty = tid >> 4, tx = tid & 15;
    float acc[8][8];
#pragma unroll
    for (int i = 0; i < 8; i++)
#pragma unroll
        for (int j = 0; j < 8; j++) acc[i][j] = 0.f;

    const float* Aptr = A  + (size_t)(oBase + aRow)*lda + aCol;
    const float* Bptr = Bm + (size_t)bRow*M_ + nBase + bCol;

    float4 av = *(const float4*)Aptr;
    float4 bv = *(const float4*)Bptr;

    for (int k0 = 0; k0 < K; k0 += 8) {
        As[aCol+0][aRow] = av.x; As[aCol+1][aRow] = av.y;
        As[aCol+2][aRow] = av.z; As[aCol+3][aRow] = av.w;
        *(float4*)&Bs[bRow][bCol] = bv;
        __syncthreads();
        if (k0 + 8 < K) {
            av = *(const float4*)(Aptr + k0 + 8);
            bv = *(const float4*)(Bptr + (size_t)(k0 + 8)*M_);
        }
#pragma unroll
        for (int k = 0; k < 8; k++) {
            float4 a0 = *(float4*)&As[k][ty*8];
            float4 a1 = *(float4*)&As[k][ty*8 + 4];
            float4 b0 = *(float4*)&Bs[k][tx*8];
            float4 b1 = *(float4*)&Bs[k][tx*8 + 4];
            float ar[8] = {a0.x, a0.y, a0.z, a0.w, a1.x, a1.y, a1.z, a1.w};
            float br[8] = {b0.x, b0.y, b0.z, b0.w, b1.x, b1.y, b1.z, b1.w};
#pragma unroll
            for (int i = 0; i < 8; i++)
#pragma unroll
                for (int j = 0; j < 8; j++) acc[i][j] += ar[i] * br[j];
        }
        __syncthreads();
    }

    int cg = nBase >> 10;   // column group (b*3+v), tile never straddles groups
#pragma unroll
    for (int i = 0; i < 8; i++) {
        int row = oBase + ty*8 + i;
        float ba = Badd ? Badd[row*24 + cg] : 0.f;
        size_t rb = (size_t)row*M_ + nBase + tx*8;
#pragma unroll
        for (int j = 0; j < 8; j += 4) {
            float4 r = make_float4(acc[i][j] + ba, acc[i][j+1] + ba,
                                   acc[i][j+2] + ba, acc[i][j+3] + ba);
            *(float4*)&Y[rb + j] = r;
        }
    }
}

// ---------------- 4b. SGEMM 64x128: Y = A @ B (+ Add elementwise) ----------------
__global__ __launch_bounds__(256, 3)
void sgemm64(const float* __restrict__ A, int lda, const float* __restrict__ Bm,
             float* __restrict__ Y, int K, const float* __restrict__ Add) {
    __shared__ float As[8][64];
    __shared__ float Bs[8][128];
    int tid = threadIdx.x;
    int nBase = blockIdx.x * 128;
    int oBase = blockIdx.y * 64;
    int aRow = tid >> 2;
    int aCol = (tid & 3) * 2;
    int bRow = tid >> 5;
    int bCol = (tid & 31) * 4;
    int ty = tid >> 4, tx = tid & 15;
    float acc[4][8];
#pragma unroll
    for (int i = 0; i < 4; i++)
#pragma unroll
        for (int j = 0; j < 8; j++) acc[i][j] = 0.f;

    const float* Aptr = A  + (size_t)(oBase + aRow)*lda + aCol;
    const float* Bptr = Bm + (size_t)bRow*M_ + nBase + bCol;

    float2 av = *(const float2*)Aptr;
    float4 bv = *(const float4*)Bptr;

    for (int k0 = 0; k0 < K; k0 += 8) {
        As[aCol+0][aRow] = av.x; As[aCol+1][aRow] = av.y;
        *(float4*)&Bs[bRow][bCol] = bv;
        __syncthreads();
        if (k0 + 8 < K) {
            av = *(const float2*)(Aptr + k0 + 8);
            bv = *(const float4*)(Bptr + (size_t)(k0 + 8)*M_);
        }
#pragma unroll
        for (int k = 0; k < 8; k++) {
            float4 a0 = *(float4*)&As[k][ty*4];
            float4 b0 = *(float4*)&Bs[k][tx*8];
            float4 b1 = *(float4*)&Bs[k][tx*8 + 4];
            float ar[4] = {a0.x, a0.y, a0.z, a0.w};
            float br[8] = {b0.x, b0.y, b0.z, b0.w, b1.x, b1.y, b1.z, b1.w};
#pragma unroll
            for (int i = 0; i < 4; i++)
#pragma unroll
                for (int j = 0; j < 8; j++) acc[i][j] += ar[i] * br[j];
        }
        __syncthreads();
    }

#pragma unroll
    for (int i = 0; i < 4; i++) {
        size_t rb = (size_t)(oBase + ty*4 + i)*M_ + nBase + tx*8;
        if (Add != nullptr) {
#pragma unroll
            for (int j = 0; j < 8; j += 4) {
                float4 ad = *(const float4*)&Add[rb + j];
                float4 r = make_float4(acc[i][j]   + ad.x, acc[i][j+1] + ad.y,
                                       acc[i][j+2] + ad.z, acc[i][j+3] + ad.w);
                *(float4*)&Y[rb + j] = r;
            }
        } else {
#pragma unroll
            for (int j = 0; j < 8; j += 4) {
                float4 r = make_float4(acc[i][j], acc[i][j+1], acc[i][j+2], acc[i][j+3]);
                *(float4*)&Y[rb + j] = r;
            }
        }
    }
}

// ---------------- 5. VN leaky-relu (slope 0), in place over D ----------------
// x: channels c<128 (or all, if P==null) from Xnet; c>=128 from pooled P (constant over n)
__global__ void lrelu_kernel(const float* __restrict__ Xnet, const float* __restrict__ P,
                             float* __restrict__ D) {
    int idx = blockIdx.x * 256 + threadIdx.x;    // over C*B_*N_
    int c = idx >> 13;
    int r = idx & 8191;
    int b = r >> 10, n = r & 1023;
    size_t base = (size_t)c*M_ + (size_t)b*3*N_ + n;
    float x0, x1, x2;
    if (P != nullptr && c >= H3) {
        int pc = (c - H3)*24 + b*3;
        x0 = P[pc]; x1 = P[pc + 1]; x2 = P[pc + 2];
    } else {
        x0 = Xnet[base]; x1 = Xnet[base + N_]; x2 = Xnet[base + 2*N_];
    }
    float d0 = D[base], d1 = D[base + N_], d2 = D[base + 2*N_];
    float dot = x0*d0 + x1*d1 + x2*d2;
    if (dot < 0.f) {
        float dd = d0*d0 + d1*d1 + d2*d2;
        float s = dot / (dd + EPSF);
        D[base]        = x0 - s*d0;
        D[base + N_]   = x1 - s*d1;
        D[base + 2*N_] = x2 - s*d2;
    } else {
        D[base] = x0; D[base + N_] = x1; D[base + 2*N_] = x2;
    }
}

// ---------------- 6. mean over points -> g_P[c][b*3+v] ----------------
__global__ void pool_kernel(const float* __restrict__ Xn) {
    int w    = blockIdx.x * 8 + (threadIdx.x >> 5);  // 0..3071 = 128*24
    int lane = threadIdx.x & 31;
    int c = w / 24; int rem = w % 24;
    size_t base = (size_t)c*M_ + (size_t)rem*N_;
    float s = 0.f;
#pragma unroll
    for (int t = 0; t < 32; t++) s += Xn[base + lane + t*32];
#pragma unroll
    for (int off = 16; off; off >>= 1) s += __shfl_xor_sync(0xffffffffu, s, off);
    if (lane == 0) g_P[c*24 + rem] = s * (1.f / N_);
}

// ---------------- 7. head: lrelu(Wd_act) + W_c ----------------
__global__ void final_kernel(const float* __restrict__ Wd, const float* __restrict__ Wc,
                             float* __restrict__ out) {
    __shared__ float s_net[H3*24];
    __shared__ float s_act[H3*24];
    int o = threadIdx.x;                     // 0..127
    for (int t = o; t < H3*24; t += 128) s_net[t] = g_P[t];
    __syncthreads();

    float dcol[24];
#pragma unroll
    for (int col = 0; col < 24; col++) dcol[col] = 0.f;
    for (int i = 0; i < H3; i++) {
        float w = Wd[o*H3 + i];
#pragma unroll
        for (int col = 0; col < 24; col++) dcol[col] += w * s_net[i*24 + col];
    }
#pragma unroll
    for (int b = 0; b < 8; b++) {
        float x0 = s_net[o*24 + b*3], x1 = s_net[o*24 + b*3 + 1], x2 = s_net[o*24 + b*3 + 2];
        float d0 = dcol[b*3], d1 = dcol[b*3 + 1], d2 = dcol[b*3 + 2];
        float dot = x0*d0 + x1*d1 + x2*d2;
        float a0 = x0, a1 = x1, a2 = x2;
        if (dot < 0.f) {
            float dd = d0*d0 + d1*d1 + d2*d2;
            float s = dot / (dd + EPSF);
            a0 = x0 - s*d0; a1 = x1 - s*d1; a2 = x2 - s*d2;
        }
        s_act[o*24 + b*3] = a0; s_act[o*24 + b*3 + 1] = a1; s_act[o*24 + b*3 + 2] = a2;
    }
    __syncthreads();

    float oc[24];
#pragma unroll
    for (int col = 0; col < 24; col++) oc[col] = 0.f;
    for (int i = 0; i < H3; i++) {
        float w = Wc[o*H3 + i];
#pragma unroll
        for (int col = 0; col < 24; col++) oc[col] += w * s_act[i*24 + col];
    }
#pragma unroll
    for (int col = 0; col < 24; col++) {
        int b = col / 3, v = col % 3;
        out[b*384 + o*3 + v] = oc[col];
    }
}

// ---------------- host ----------------
static float* symaddr(const void* sym) {
    void* p = nullptr;
    cudaGetSymbolAddress(&p, sym);
    return (float*)p;
}

extern "C" void kernel_launch(void* const* d_in, const int* in_sizes, int n_in,
                              void* d_out, int out_size) {
    const float* p      = (const float*)d_in[0];
    const float* Wpos   = (const float*)d_in[1];
    const float* Wd0s   = (const float*)d_in[2];
    const float* W0s    = (const float*)d_in[3];
    const float* Wd1s   = (const float*)d_in[4];
    const float* W1s    = (const float*)d_in[5];
    const float* Wss    = (const float*)d_in[6];
    const float* Wd_act = (const float*)d_in[7];
    const float* Wc     = (const float*)d_in[8];
    float* out = (float*)d_out;

    float* X0   = symaddr(g_X0);
    float* DS   = symaddr(g_DS);
    float* S    = DS + (size_t)C2*M_;       // rows 256..383 of DS
    float* Nt   = symaddr(g_Nt);
    float* D1   = symaddr(g_D1);
    float* Wcat = symaddr(g_Wcat);
    float* Badd = symaddr(g_Badd);

    center_kernel<<<B_, 256>>>(p);
    knn_mean_kernel<<<B_*4, 256>>>();
    featpos_kernel<<<B_*3*8, 256>>>(Wpos);
    wcat_kernel<<<(5*384*C2)/256, 256>>>(Wd0s, Wss);

    for (int i = 0; i < 5; i++) {
        const float* Wc_i = Wcat + (size_t)i*384*C2;
        const float* W0  = W0s  + (size_t)i*H3*C2;
        const float* Wd1 = Wd1s + (size_t)i*H3*H3;
        const float* W1  = W1s  + (size_t)i*H3*H3;

        if (i == 0) {
            // D;S = [Wd0; Ws] @ X0  (full K=256)
            sgemm128<<<dim3(192, 3), 256>>>(Wc_i, C2, X0, DS, C2, nullptr);
        } else {
            // Badd = [Wd0;Ws][:,128:] @ P ;  D;S = [Wd0;Ws][:, :128] @ netX + Badd
            badd_kernel<<<36, 256>>>(Wc_i);
            sgemm128<<<dim3(192, 3), 256>>>(Wc_i, C2, X0, DS, H3, Badd);
        }
        // D = lrelu(X, D)  (256 ch; for i>0 channels 128..255 come from P)
        lrelu_kernel<<<(C2*8192)/256, 256>>>(X0, (i == 0) ? nullptr : symaddr(g_P), DS);
        // Nt = W0 @ D  (K=256)
        sgemm64<<<dim3(192, 2), 256>>>(W0, C2, DS, Nt, C2, nullptr);
        // D1 = Wd1 @ Nt  (K=128)
        sgemm64<<<dim3(192, 2), 256>>>(Wd1, H3, Nt, D1, H3, nullptr);
        // D1 = lrelu(Nt, D1)  (128 ch)
        lrelu_kernel<<<(H3*8192)/256, 256>>>(Nt, nullptr, D1);
        // netX = W1 @ D1 + S  (in-place into X0 rows 0..127)
        sgemm64<<<dim3(192, 2), 256>>>(W1, H3, D1, X0, H3, S);
        // P = mean over points (also the final pool when i==4)
        pool_kernel<<<384, 256>>>(X0);
    }

    final_kernel<<<1, 128>>>(Wd_act, Wc, out);
}

// round 4
// speedup vs baseline: 1.5362x; 1.3453x over previous
#include <cuda_runtime.h>
#include <cstdint>

#define B_   8
#define N_   1024
#define M_   24576      // B_*3*N_
#define C2   256
#define H3   128
#define KNN_ 20
#define EPSF 1e-6f

// ---------------- scratch (allocation-free: __device__ globals) ----------------
__device__ float g_pc[B_*N_*3];       // centered points
__device__ float g_m [B_*N_*3];       // mean of 20-NN per point
__device__ float g_X0[C2*M_];         // pos features (256 rows); rows 0..127 reused as netX
__device__ float g_DS[384*M_];        // GEMM1 output: rows 0..255 = D, 256..383 = S = Ws@X
__device__ float g_Nt[H3*M_];
__device__ float g_D1[H3*M_];
__device__ float g_P [H3*24];         // pooled per (c, b*3+v)
__device__ float g_Wcat[5*384*C2];    // [Wd0; Ws] per block
__device__ float g_Badd[384*24];      // [Wd0;Ws][:,128:] @ P

// ---------------- tf32 helpers ----------------
__device__ __forceinline__ void split_tf32(float x, uint32_t& hi, uint32_t& lo) {
    asm("cvt.rna.tf32.f32 %0, %1;" : "=r"(hi) : "f"(x));
    float r = x - __uint_as_float(hi);
    asm("cvt.rna.tf32.f32 %0, %1;" : "=r"(lo) : "f"(r));
}
__device__ __forceinline__ void mma8(float* c, const uint32_t* a, const uint32_t* b) {
    asm volatile("mma.sync.aligned.m16n8k8.row.col.f32.tf32.tf32.f32 "
        "{%0,%1,%2,%3}, {%4,%5,%6,%7}, {%8,%9}, {%0,%1,%2,%3};"
        : "+f"(c[0]), "+f"(c[1]), "+f"(c[2]), "+f"(c[3])
        : "r"(a[0]), "r"(a[1]), "r"(a[2]), "r"(a[3]), "r"(b[0]), "r"(b[1]));
}
__device__ __forceinline__ void cp16(float* smem, const float* g) {
    uint32_t s = (uint32_t)__cvta_generic_to_shared(smem);
    asm volatile("cp.async.cg.shared.global [%0], [%1], 16;" :: "r"(s), "l"(g));
}

// ---------------- 1. center per cloud ----------------
__global__ void center_kernel(const float* __restrict__ p) {
    int b = blockIdx.x;
    __shared__ float s[3][256];
    float s0 = 0.f, s1 = 0.f, s2 = 0.f;
    for (int n = threadIdx.x; n < N_; n += 256) {
        const float* q = p + (size_t)(b*N_ + n)*3;
        s0 += q[0]; s1 += q[1]; s2 += q[2];
    }
    s[0][threadIdx.x] = s0; s[1][threadIdx.x] = s1; s[2][threadIdx.x] = s2;
    __syncthreads();
    for (int st = 128; st > 0; st >>= 1) {
        if (threadIdx.x < st) {
            s[0][threadIdx.x] += s[0][threadIdx.x + st];
            s[1][threadIdx.x] += s[1][threadIdx.x + st];
            s[2][threadIdx.x] += s[2][threadIdx.x + st];
        }
        __syncthreads();
    }
    float m0 = s[0][0] / N_, m1 = s[1][0] / N_, m2 = s[2][0] / N_;
    for (int n = threadIdx.x; n < N_; n += 256) {
        const float* q = p + (size_t)(b*N_ + n)*3;
        float* o = g_pc + (size_t)(b*N_ + n)*3;
        o[0] = q[0] - m0; o[1] = q[1] - m1; o[2] = q[2] - m2;
    }
}

// ---------------- 2. KNN (k=20, self included) -> mean of neighbor coords ----------------
__global__ void knn_mean_kernel() {
    int b     = blockIdx.x >> 2;
    int chunk = blockIdx.x & 3;
    __shared__ float sp[N_*3];
    __shared__ float sxx[N_];
    for (int t = threadIdx.x; t < N_*3; t += 256) sp[t] = g_pc[b*N_*3 + t];
    __syncthreads();
    for (int t = threadIdx.x; t < N_; t += 256) {
        float x = sp[t*3], y = sp[t*3+1], z = sp[t*3+2];
        sxx[t] = x*x + y*y + z*z;
    }
    __syncthreads();

    int i = chunk*256 + threadIdx.x;
    float xi = sp[i*3], yi = sp[i*3+1], zi = sp[i*3+2];
    float xxi = sxx[i];

    float bd[KNN_]; int bi[KNN_];
#pragma unroll
    for (int t = 0; t < KNN_; t++) { bd[t] = -3.4e38f; bi[t] = 0; }

    for (int j = 0; j < N_; j++) {
        float dot = xi*sp[j*3] + yi*sp[j*3+1] + zi*sp[j*3+2];
        float nd  = 2.f*dot - xxi - sxx[j];
        if (nd > bd[KNN_-1]) {                      // strict > => ties keep lower index
            int t = KNN_-1;
            while (t > 0 && bd[t-1] < nd) { bd[t] = bd[t-1]; bi[t] = bi[t-1]; t--; }
            bd[t] = nd; bi[t] = j;
        }
    }
    float m0 = 0.f, m1 = 0.f, m2 = 0.f;
#pragma unroll
    for (int t = 0; t < KNN_; t++) {
        int j = bi[t];
        m0 += sp[j*3]; m1 += sp[j*3+1]; m2 += sp[j*3+2];
    }
    float* o = g_m + (size_t)(b*N_ + i)*3;
    o[0] = m0 / KNN_; o[1] = m1 / KNN_; o[2] = m2 / KNN_;
}

// ---------------- 3. fused edge-feature + W_pos + pool_k -> g_X0 ----------------
__global__ void featpos_kernel(const float* __restrict__ Wpos) {
    int bk = blockIdx.x;                 // 0..191 = b(8) * v(3) * chunk(8)
    int b = bk / 24; int rem = bk % 24;
    int v = rem / 8; int chunk = rem % 8;
    int n0 = chunk * 128;
    __shared__ float f0[128], f1[128], f2[128];
    if (threadIdx.x < 128) {
        int n = n0 + threadIdx.x;
        const float* pp = g_pc + (size_t)(b*N_ + n)*3;
        const float* mm = g_m  + (size_t)(b*N_ + n)*3;
        float p0 = pp[0], p1 = pp[1], p2 = pp[2];
        float m0 = mm[0], m1 = mm[1], m2 = mm[2];
        float pv = (v == 0) ? p0 : ((v == 1) ? p1 : p2);
        float mv = (v == 0) ? m0 : ((v == 1) ? m1 : m2);
        float cv;
        if (v == 0)      cv = m1*p2 - m2*p1;
        else if (v == 1) cv = m2*p0 - m0*p2;
        else             cv = m0*p1 - m1*p0;
        f0[threadIdx.x] = mv - pv;
        f1[threadIdx.x] = pv;
        f2[threadIdx.x] = cv;
    }
    __syncthreads();
    int nl = threadIdx.x & 127;
    int oo = threadIdx.x >> 7;
    size_t colbase = (size_t)(b*3 + v)*N_ + n0;
    for (int ob = 0; ob < C2; ob += 2) {
        int o = ob + oo;
        float w0 = Wpos[o*3], w1 = Wpos[o*3+1], w2 = Wpos[o*3+2];
        g_X0[(size_t)o*M_ + colbase + nl] = w0*f0[nl] + w1*f1[nl] + w2*f2[nl];
    }
}

// ---------------- 3b. build concatenated [Wd0; Ws] weights ----------------
__global__ void wcat_kernel(const float* __restrict__ Wd0s, const float* __restrict__ Wss) {
    int idx = blockIdx.x * 256 + threadIdx.x;   // 5*384*256
    int i   = idx / (384*C2);
    int rem = idx % (384*C2);
    int r = rem / C2, c = rem % C2;
    float v = (r < C2) ? Wd0s[(size_t)i*C2*C2 + r*C2 + c]
                       : Wss [(size_t)i*H3*C2 + (r - C2)*C2 + c];
    g_Wcat[idx] = v;
}

// ---------------- 3c. Badd[384][24] = Wcat[:,128:] @ P ----------------
__global__ void badd_kernel(const float* __restrict__ Wcat) {
    int idx = blockIdx.x * 256 + threadIdx.x;   // 384*24 = 9216
    if (idx >= 384*24) return;
    int r = idx / 24, cg = idx % 24;
    float s = 0.f;
#pragma unroll 8
    for (int k = 0; k < H3; k++)
        s += Wcat[r*C2 + H3 + k] * g_P[k*24 + cg];
    g_Badd[idx] = s;
}

// ---------------- 4. tf32 tensor-core GEMM (3xTF32): Y = A[.,lda] @ B[K,M_] ----------------
// block tile 128(M) x 64(N), BK=16, 8 warps (4x2), warp tile 32x32
__global__ __launch_bounds__(256, 2)
void gemm_tf32(const float* __restrict__ A, int lda, const float* __restrict__ Bm,
               float* __restrict__ Y, int K, const float* __restrict__ Badd,
               const float* __restrict__ Add)
{
    const int WA = 20, WB = 72;
    __shared__ float As[2][128*WA];
    __shared__ float Bs[2][16*WB];
    int tid  = threadIdx.x;
    int lane = tid & 31, wid = tid >> 5;
    int warp_m = wid >> 1, warp_n = wid & 1;
    int gid = lane >> 2, tig = lane & 3;
    int nBase = blockIdx.x * 64;
    int oBase = blockIdx.y * 128;

    int am  = tid >> 2,  ak4 = (tid & 3) * 4;   // A loader: rows am, am+64
    int brr = tid >> 4,  bc4 = (tid & 15) * 4;  // B loader

    const float* Ag = A + (size_t)oBase * lda;
    int stages = K >> 4;

    float c[2][4][4];
#pragma unroll
    for (int mt = 0; mt < 2; mt++)
#pragma unroll
        for (int nt = 0; nt < 4; nt++)
#pragma unroll
            for (int r = 0; r < 4; r++) c[mt][nt][r] = 0.f;

#define LOAD_STAGE(s, buf)                                                        \
    do {                                                                          \
        int k0_ = (s) * 16;                                                       \
        cp16(&As[buf][am*WA + ak4],      Ag + (size_t)am*lda + k0_ + ak4);        \
        cp16(&As[buf][(am+64)*WA + ak4], Ag + (size_t)(am+64)*lda + k0_ + ak4);   \
        cp16(&Bs[buf][brr*WB + bc4],     Bm + (size_t)(k0_ + brr)*M_ + nBase + bc4); \
        asm volatile("cp.async.commit_group;");                                   \
    } while (0)

    LOAD_STAGE(0, 0);
    LOAD_STAGE(1, 1);

    for (int s = 0; s < stages; s++) {
        asm volatile("cp.async.wait_group 1;");
        __syncthreads();
        int buf = s & 1;
#pragma unroll
        for (int ks = 0; ks < 2; ks++) {
            int k0 = ks * 8;
            uint32_t ah[2][4], al[2][4];
#pragma unroll
            for (int mt = 0; mt < 2; mt++) {
                int mr = warp_m*32 + mt*16 + gid;
                float a0 = As[buf][(mr    )*WA + k0 + tig];
                float a1 = As[buf][(mr + 8)*WA + k0 + tig];
                float a2 = As[buf][(mr    )*WA + k0 + tig + 4];
                float a3 = As[buf][(mr + 8)*WA + k0 + tig + 4];
                split_tf32(a0, ah[mt][0], al[mt][0]);
                split_tf32(a1, ah[mt][1], al[mt][1]);
                split_tf32(a2, ah[mt][2], al[mt][2]);
                split_tf32(a3, ah[mt][3], al[mt][3]);
            }
            uint32_t bh[4][2], bl[4][2];
#pragma unroll
            for (int nt = 0; nt < 4; nt++) {
                int nc = warp_n*32 + nt*8 + gid;
                float b0 = Bs[buf][(k0 + tig    )*WB + nc];
                float b1 = Bs[buf][(k0 + tig + 4)*WB + nc];
                split_tf32(b0, bh[nt][0], bl[nt][0]);
                split_tf32(b1, bh[nt][1], bl[nt][1]);
            }
#pragma unroll
            for (int mt = 0; mt < 2; mt++)
#pragma unroll
                for (int nt = 0; nt < 4; nt++) {
                    mma8(c[mt][nt], ah[mt], bl[nt]);   // hi*lo
                    mma8(c[mt][nt], al[mt], bh[nt]);   // lo*hi
                    mma8(c[mt][nt], ah[mt], bh[nt]);   // hi*hi
                }
        }
        __syncthreads();
        if (s + 2 < stages) LOAD_STAGE(s + 2, buf);
    }
#undef LOAD_STAGE

    int cg = nBase >> 10;   // column group (b*3+v); tile never straddles groups
#pragma unroll
    for (int mt = 0; mt < 2; mt++) {
#pragma unroll
        for (int nt = 0; nt < 4; nt++) {
            int r0 = oBase + warp_m*32 + mt*16 + gid;
            int r1 = r0 + 8;
            int col = nBase + warp_n*32 + nt*8 + tig*2;
            float* cc = c[mt][nt];
            float ba0 = 0.f, ba1 = 0.f;
            if (Badd) { ba0 = Badd[r0*24 + cg]; ba1 = Badd[r1*24 + cg]; }
            size_t p0 = (size_t)r0*M_ + col;
            size_t p1 = (size_t)r1*M_ + col;
            float o0 = cc[0] + ba0, o1 = cc[1] + ba0;
            float o2 = cc[2] + ba1, o3 = cc[3] + ba1;
            if (Add) {
                float2 t0 = *(const float2*)&Add[p0];
                float2 t1 = *(const float2*)&Add[p1];
                o0 += t0.x; o1 += t0.y; o2 += t1.x; o3 += t1.y;
            }
            *(float2*)&Y[p0] = make_float2(o0, o1);
            *(float2*)&Y[p1] = make_float2(o2, o3);
        }
    }
}

// ---------------- 5. VN leaky-relu (slope 0), in place over D ----------------
__global__ void lrelu_kernel(const float* __restrict__ Xnet, const float* __restrict__ P,
                             float* __restrict__ D) {
    int idx = blockIdx.x * 256 + threadIdx.x;    // over C*B_*N_
    int c = idx >> 13;
    int r = idx & 8191;
    int b = r >> 10, n = r & 1023;
    size_t base = (size_t)c*M_ + (size_t)b*3*N_ + n;
    float x0, x1, x2;
    if (P != nullptr && c >= H3) {
        int pc = (c - H3)*24 + b*3;
        x0 = P[pc]; x1 = P[pc + 1]; x2 = P[pc + 2];
    } else {
        x0 = Xnet[base]; x1 = Xnet[base + N_]; x2 = Xnet[base + 2*N_];
    }
    float d0 = D[base], d1 = D[base + N_], d2 = D[base + 2*N_];
    float dot = x0*d0 + x1*d1 + x2*d2;
    if (dot < 0.f) {
        float dd = d0*d0 + d1*d1 + d2*d2;
        float s = dot / (dd + EPSF);
        D[base]        = x0 - s*d0;
        D[base + N_]   = x1 - s*d1;
        D[base + 2*N_] = x2 - s*d2;
    } else {
        D[base] = x0; D[base + N_] = x1; D[base + 2*N_] = x2;
    }
}

// ---------------- 6. mean over points -> g_P[c][b*3+v] ----------------
__global__ void pool_kernel(const float* __restrict__ Xn) {
    int w    = blockIdx.x * 8 + (threadIdx.x >> 5);  // 0..3071 = 128*24
    int lane = threadIdx.x & 31;
    int c = w / 24; int rem = w % 24;
    size_t base = (size_t)c*M_ + (size_t)rem*N_;
    float s = 0.f;
#pragma unroll
    for (int t = 0; t < 32; t++) s += Xn[base + lane + t*32];
#pragma unroll
    for (int off = 16; off; off >>= 1) s += __shfl_xor_sync(0xffffffffu, s, off);
    if (lane == 0) g_P[c*24 + rem] = s * (1.f / N_);
}

// ---------------- 7. head: lrelu(Wd_act) + W_c ----------------
__global__ void final_kernel(const float* __restrict__ Wd, const float* __restrict__ Wc,
                             float* __restrict__ out) {
    __shared__ float s_net[H3*24];
    __shared__ float s_act[H3*24];
    int o = threadIdx.x;                     // 0..127
    for (int t = o; t < H3*24; t += 128) s_net[t] = g_P[t];
    __syncthreads();

    float dcol[24];
#pragma unroll
    for (int col = 0; col < 24; col++) dcol[col] = 0.f;
    for (int i = 0; i < H3; i++) {
        float w = Wd[o*H3 + i];
#pragma unroll
        for (int col = 0; col < 24; col++) dcol[col] += w * s_net[i*24 + col];
    }
#pragma unroll
    for (int b = 0; b < 8; b++) {
        float x0 = s_net[o*24 + b*3], x1 = s_net[o*24 + b*3 + 1], x2 = s_net[o*24 + b*3 + 2];
        float d0 = dcol[b*3], d1 = dcol[b*3 + 1], d2 = dcol[b*3 + 2];
        float dot = x0*d0 + x1*d1 + x2*d2;
        float a0 = x0, a1 = x1, a2 = x2;
        if (dot < 0.f) {
            float dd = d0*d0 + d1*d1 + d2*d2;
            float s = dot / (dd + EPSF);
            a0 = x0 - s*d0; a1 = x1 - s*d1; a2 = x2 - s*d2;
        }
        s_act[o*24 + b*3] = a0; s_act[o*24 + b*3 + 1] = a1; s_act[o*24 + b*3 + 2] = a2;
    }
    __syncthreads();

    float oc[24];
#pragma unroll
    for (int col = 0; col < 24; col++) oc[col] = 0.f;
    for (int i = 0; i < H3; i++) {
        float w = Wc[o*H3 + i];
#pragma unroll
        for (int col = 0; col < 24; col++) oc[col] += w * s_act[i*24 + col];
    }
#pragma unroll
    for (int col = 0; col < 24; col++) {
        int b = col / 3, v = col % 3;
        out[b*384 + o*3 + v] = oc[col];
    }
}

// ---------------- host ----------------
static float* symaddr(const void* sym) {
    void* p = nullptr;
    cudaGetSymbolAddress(&p, sym);
    return (float*)p;
}

extern "C" void kernel_launch(void* const* d_in, const int* in_sizes, int n_in,
                              void* d_out, int out_size) {
    const float* p      = (const float*)d_in[0];
    const float* Wpos   = (const float*)d_in[1];
    const float* Wd0s   = (const float*)d_in[2];
    const float* W0s    = (const float*)d_in[3];
    const float* Wd1s   = (const float*)d_in[4];
    const float* W1s    = (const float*)d_in[5];
    const float* Wss    = (const float*)d_in[6];
    const float* Wd_act = (const float*)d_in[7];
    const float* Wc     = (const float*)d_in[8];
    float* out = (float*)d_out;

    float* X0   = symaddr(g_X0);
    float* DS   = symaddr(g_DS);
    float* S    = DS + (size_t)C2*M_;       // rows 256..383 of DS
    float* Nt   = symaddr(g_Nt);
    float* D1   = symaddr(g_D1);
    float* Wcat = symaddr(g_Wcat);
    float* Badd = symaddr(g_Badd);

    center_kernel<<<B_, 256>>>(p);
    knn_mean_kernel<<<B_*4, 256>>>();
    featpos_kernel<<<B_*3*8, 256>>>(Wpos);
    wcat_kernel<<<(5*384*C2)/256, 256>>>(Wd0s, Wss);

    for (int i = 0; i < 5; i++) {
        const float* Wc_i = Wcat + (size_t)i*384*C2;
        const float* W0  = W0s  + (size_t)i*H3*C2;
        const float* Wd1 = Wd1s + (size_t)i*H3*H3;
        const float* W1  = W1s  + (size_t)i*H3*H3;

        if (i == 0) {
            // D;S = [Wd0; Ws] @ X0  (full K=256)
            gemm_tf32<<<dim3(384, 3), 256>>>(Wc_i, C2, X0, DS, C2, nullptr, nullptr);
        } else {
            // Badd = [Wd0;Ws][:,128:] @ P ;  D;S = [Wd0;Ws][:, :128] @ netX + Badd
            badd_kernel<<<36, 256>>>(Wc_i);
            gemm_tf32<<<dim3(384, 3), 256>>>(Wc_i, C2, X0, DS, H3, Badd, nullptr);
        }
        // D = lrelu(X, D)  (256 ch; for i>0 channels 128..255 come from P)
        lrelu_kernel<<<(C2*8192)/256, 256>>>(X0, (i == 0) ? nullptr : symaddr(g_P), DS);
        // Nt = W0 @ D  (K=256)
        gemm_tf32<<<dim3(384, 1), 256>>>(W0, C2, DS, Nt, C2, nullptr, nullptr);
        // D1 = Wd1 @ Nt  (K=128)
        gemm_tf32<<<dim3(384, 1), 256>>>(Wd1, H3, Nt, D1, H3, nullptr, nullptr);
        // D1 = lrelu(Nt, D1)  (128 ch)
        lrelu_kernel<<<(H3*8192)/256, 256>>>(Nt, nullptr, D1);
        // netX = W1 @ D1 + S  (in-place into X0 rows 0..127)
        gemm_tf32<<<dim3(384, 1), 256>>>(W1, H3, D1, X0, H3, nullptr, S);
        // P = mean over points (also the final pool when i==4)
        pool_kernel<<<384, 256>>>(X0);
    }

    final_kernel<<<1, 128>>>(Wd_act, Wc, out);
}

// round 5
// speedup vs baseline: 1.5417x; 1.0035x over previous
#include <cuda_runtime.h>
#include <cstdint>

#define B_   8
#define N_   1024
#define M_   24576      // B_*3*N_
#define C2   256
#define H3   128
#define KNN_ 20
#define EPSF 1e-6f

// ---------------- scratch (allocation-free: __device__ globals) ----------------
__device__ float g_pc[B_*N_*3];       // centered points
__device__ float g_m [B_*N_*3];       // mean of 20-NN per point
__device__ float g_X0[C2*M_];         // pos features (256 rows); rows 0..127 reused as netX
__device__ float g_DS[384*M_];        // GEMM1 output: rows 0..255 = D, 256..383 = S = Ws@X
__device__ float g_Nt[H3*M_];
__device__ float g_D1[H3*M_];
__device__ float g_P [H3*24];         // pooled per (c, b*3+v)
__device__ float g_Wcat[5*384*C2];    // [Wd0; Ws] per block
__device__ float g_Badd[384*24];      // [Wd0;Ws][:,128:] @ P

// ---------------- tf32 helpers ----------------
__device__ __forceinline__ void split_tf32(float x, uint32_t& hi, uint32_t& lo) {
    asm("cvt.rna.tf32.f32 %0, %1;" : "=r"(hi) : "f"(x));
    float r = x - __uint_as_float(hi);
    asm("cvt.rna.tf32.f32 %0, %1;" : "=r"(lo) : "f"(r));
}
__device__ __forceinline__ void mma8(float* c, const uint32_t* a, const uint32_t* b) {
    asm volatile("mma.sync.aligned.m16n8k8.row.col.f32.tf32.tf32.f32 "
        "{%0,%1,%2,%3}, {%4,%5,%6,%7}, {%8,%9}, {%0,%1,%2,%3};"
        : "+f"(c[0]), "+f"(c[1]), "+f"(c[2]), "+f"(c[3])
        : "r"(a[0]), "r"(a[1]), "r"(a[2]), "r"(a[3]), "r"(b[0]), "r"(b[1]));
}
__device__ __forceinline__ void cp16(float* smem, const float* g) {
    uint32_t s = (uint32_t)__cvta_generic_to_shared(smem);
    asm volatile("cp.async.cg.shared.global [%0], [%1], 16;" :: "r"(s), "l"(g));
}

// ---------------- 1. center per cloud ----------------
__global__ void center_kernel(const float* __restrict__ p) {
    int b = blockIdx.x;
    __shared__ float s[3][256];
    float s0 = 0.f, s1 = 0.f, s2 = 0.f;
    for (int n = threadIdx.x; n < N_; n += 256) {
        const float* q = p + (size_t)(b*N_ + n)*3;
        s0 += q[0]; s1 += q[1]; s2 += q[2];
    }
    s[0][threadIdx.x] = s0; s[1][threadIdx.x] = s1; s[2][threadIdx.x] = s2;
    __syncthreads();
    for (int st = 128; st > 0; st >>= 1) {
        if (threadIdx.x < st) {
            s[0][threadIdx.x] += s[0][threadIdx.x + st];
            s[1][threadIdx.x] += s[1][threadIdx.x + st];
            s[2][threadIdx.x] += s[2][threadIdx.x + st];
        }
        __syncthreads();
    }
    float m0 = s[0][0] / N_, m1 = s[1][0] / N_, m2 = s[2][0] / N_;
    for (int n = threadIdx.x; n < N_; n += 256) {
        const float* q = p + (size_t)(b*N_ + n)*3;
        float* o = g_pc + (size_t)(b*N_ + n)*3;
        o[0] = q[0] - m0; o[1] = q[1] - m1; o[2] = q[2] - m2;
    }
}

// ---------------- 2. KNN (k=20, self included) -> mean of neighbor coords ----------------
__global__ void knn_mean_kernel() {
    int b     = blockIdx.x >> 2;
    int chunk = blockIdx.x & 3;
    __shared__ float sp[N_*3];
    __shared__ float sxx[N_];
    for (int t = threadIdx.x; t < N_*3; t += 256) sp[t] = g_pc[b*N_*3 + t];
    __syncthreads();
    for (int t = threadIdx.x; t < N_; t += 256) {
        float x = sp[t*3], y = sp[t*3+1], z = sp[t*3+2];
        sxx[t] = x*x + y*y + z*z;
    }
    __syncthreads();

    int i = chunk*256 + threadIdx.x;
    float xi = sp[i*3], yi = sp[i*3+1], zi = sp[i*3+2];
    float xxi = sxx[i];

    float bd[KNN_]; int bi[KNN_];
#pragma unroll
    for (int t = 0; t < KNN_; t++) { bd[t] = -3.4e38f; bi[t] = 0; }

    for (int j = 0; j < N_; j++) {
        float dot = xi*sp[j*3] + yi*sp[j*3+1] + zi*sp[j*3+2];
        float nd  = 2.f*dot - xxi - sxx[j];
        if (nd > bd[KNN_-1]) {                      // strict > => ties keep lower index
            int t = KNN_-1;
            while (t > 0 && bd[t-1] < nd) { bd[t] = bd[t-1]; bi[t] = bi[t-1]; t--; }
            bd[t] = nd; bi[t] = j;
        }
    }
    float m0 = 0.f, m1 = 0.f, m2 = 0.f;
#pragma unroll
    for (int t = 0; t < KNN_; t++) {
        int j = bi[t];
        m0 += sp[j*3]; m1 += sp[j*3+1]; m2 += sp[j*3+2];
    }
    float* o = g_m + (size_t)(b*N_ + i)*3;
    o[0] = m0 / KNN_; o[1] = m1 / KNN_; o[2] = m2 / KNN_;
}

// ---------------- 3. fused edge-feature + W_pos + pool_k -> g_X0 ----------------
__global__ void featpos_kernel(const float* __restrict__ Wpos) {
    int bk = blockIdx.x;                 // 0..191 = b(8) * v(3) * chunk(8)
    int b = bk / 24; int rem = bk % 24;
    int v = rem / 8; int chunk = rem % 8;
    int n0 = chunk * 128;
    __shared__ float f0[128], f1[128], f2[128];
    if (threadIdx.x < 128) {
        int n = n0 + threadIdx.x;
        const float* pp = g_pc + (size_t)(b*N_ + n)*3;
        const float* mm = g_m  + (size_t)(b*N_ + n)*3;
        float p0 = pp[0], p1 = pp[1], p2 = pp[2];
        float m0 = mm[0], m1 = mm[1], m2 = mm[2];
        float pv = (v == 0) ? p0 : ((v == 1) ? p1 : p2);
        float mv = (v == 0) ? m0 : ((v == 1) ? m1 : m2);
        float cv;
        if (v == 0)      cv = m1*p2 - m2*p1;
        else if (v == 1) cv = m2*p0 - m0*p2;
        else             cv = m0*p1 - m1*p0;
        f0[threadIdx.x] = mv - pv;
        f1[threadIdx.x] = pv;
        f2[threadIdx.x] = cv;
    }
    __syncthreads();
    int nl = threadIdx.x & 127;
    int oo = threadIdx.x >> 7;
    size_t colbase = (size_t)(b*3 + v)*N_ + n0;
    for (int ob = 0; ob < C2; ob += 2) {
        int o = ob + oo;
        float w0 = Wpos[o*3], w1 = Wpos[o*3+1], w2 = Wpos[o*3+2];
        g_X0[(size_t)o*M_ + colbase + nl] = w0*f0[nl] + w1*f1[nl] + w2*f2[nl];
    }
}

// ---------------- 3b. build concatenated [Wd0; Ws] weights ----------------
__global__ void wcat_kernel(const float* __restrict__ Wd0s, const float* __restrict__ Wss) {
    int idx = blockIdx.x * 256 + threadIdx.x;   // 5*384*256
    int i   = idx / (384*C2);
    int rem = idx % (384*C2);
    int r = rem / C2, c = rem % C2;
    float v = (r < C2) ? Wd0s[(size_t)i*C2*C2 + r*C2 + c]
                       : Wss [(size_t)i*H3*C2 + (r - C2)*C2 + c];
    g_Wcat[idx] = v;
}

// ---------------- 3c. Badd[384][24] = Wcat[:,128:] @ P ----------------
__global__ void badd_kernel(const float* __restrict__ Wcat) {
    int idx = blockIdx.x * 256 + threadIdx.x;   // 384*24 = 9216
    if (idx >= 384*24) return;
    int r = idx / 24, cg = idx % 24;
    float s = 0.f;
#pragma unroll 8
    for (int k = 0; k < H3; k++)
        s += Wcat[r*C2 + H3 + k] * g_P[k*24 + cg];
    g_Badd[idx] = s;
}

// ---------------- 4. tf32 tensor-core GEMM (3xTF32): Y = A[.,lda] @ B[K,M_] ----------------
// block tile 128(M) x 64(N), BK=16, 8 warps (4x2), warp tile 32x32
__global__ __launch_bounds__(256, 2)
void gemm_tf32(const float* __restrict__ A, int lda, const float* __restrict__ Bm,
               float* __restrict__ Y, int K, const float* __restrict__ Badd,
               const float* __restrict__ Add)
{
    const int WA = 20, WB = 72;
    __shared__ float As[2][128*WA];
    __shared__ float Bs[2][16*WB];
    int tid  = threadIdx.x;
    int lane = tid & 31, wid = tid >> 5;
    int warp_m = wid >> 1, warp_n = wid & 1;
    int gid = lane >> 2, tig = lane & 3;
    int nBase = blockIdx.x * 64;
    int oBase = blockIdx.y * 128;

    int am  = tid >> 2,  ak4 = (tid & 3) * 4;   // A loader: rows am, am+64
    int brr = tid >> 4,  bc4 = (tid & 15) * 4;  // B loader

    const float* Ag = A + (size_t)oBase * lda;
    int stages = K >> 4;

    float c[2][4][4];
#pragma unroll
    for (int mt = 0; mt < 2; mt++)
#pragma unroll
        for (int nt = 0; nt < 4; nt++)
#pragma unroll
            for (int r = 0; r < 4; r++) c[mt][nt][r] = 0.f;

#define LOAD_STAGE(s, buf)                                                        \
    do {                                                                          \
        int k0_ = (s) * 16;                                                       \
        cp16(&As[buf][am*WA + ak4],      Ag + (size_t)am*lda + k0_ + ak4);        \
        cp16(&As[buf][(am+64)*WA + ak4], Ag + (size_t)(am+64)*lda + k0_ + ak4);   \
        cp16(&Bs[buf][brr*WB + bc4],     Bm + (size_t)(k0_ + brr)*M_ + nBase + bc4); \
        asm volatile("cp.async.commit_group;");                                   \
    } while (0)

    LOAD_STAGE(0, 0);
    LOAD_STAGE(1, 1);

    for (int s = 0; s < stages; s++) {
        asm volatile("cp.async.wait_group 1;");
        __syncthreads();
        int buf = s & 1;
#pragma unroll
        for (int ks = 0; ks < 2; ks++) {
            int k0 = ks * 8;
            uint32_t ah[2][4], al[2][4];
#pragma unroll
            for (int mt = 0; mt < 2; mt++) {
                int mr = warp_m*32 + mt*16 + gid;
                float a0 = As[buf][(mr    )*WA + k0 + tig];
                float a1 = As[buf][(mr + 8)*WA + k0 + tig];
                float a2 = As[buf][(mr    )*WA + k0 + tig + 4];
                float a3 = As[buf][(mr + 8)*WA + k0 + tig + 4];
                split_tf32(a0, ah[mt][0], al[mt][0]);
                split_tf32(a1, ah[mt][1], al[mt][1]);
                split_tf32(a2, ah[mt][2], al[mt][2]);
                split_tf32(a3, ah[mt][3], al[mt][3]);
            }
            uint32_t bh[4][2], bl[4][2];
#pragma unroll
            for (int nt = 0; nt < 4; nt++) {
                int nc = warp_n*32 + nt*8 + gid;
                float b0 = Bs[buf][(k0 + tig    )*WB + nc];
                float b1 = Bs[buf][(k0 + tig + 4)*WB + nc];
                split_tf32(b0, bh[nt][0], bl[nt][0]);
                split_tf32(b1, bh[nt][1], bl[nt][1]);
            }
#pragma unroll
            for (int mt = 0; mt < 2; mt++)
#pragma unroll
                for (int nt = 0; nt < 4; nt++) {
                    mma8(c[mt][nt], ah[mt], bl[nt]);   // hi*lo
                    mma8(c[mt][nt], al[mt], bh[nt]);   // lo*hi
                    mma8(c[mt][nt], ah[mt], bh[nt]);   // hi*hi
                }
        }
        __syncthreads();
        if (s + 2 < stages) LOAD_STAGE(s + 2, buf);
    }
#undef LOAD_STAGE

    int cg = nBase >> 10;   // column group (b*3+v); tile never straddles groups
#pragma unroll
    for (int mt = 0; mt < 2; mt++) {
#pragma unroll
        for (int nt = 0; nt < 4; nt++) {
            int r0 = oBase + warp_m*32 + mt*16 + gid;
            int r1 = r0 + 8;
            int col = nBase + warp_n*32 + nt*8 + tig*2;
            float* cc = c[mt][nt];
            float ba0 = 0.f, ba1 = 0.f;
            if (Badd) { ba0 = Badd[r0*24 + cg]; ba1 = Badd[r1*24 + cg]; }
            size_t p0 = (size_t)r0*M_ + col;
            size_t p1 = (size_t)r1*M_ + col;
            float o0 = cc[0] + ba0, o1 = cc[1] + ba0;
            float o2 = cc[2] + ba1, o3 = cc[3] + ba1;
            if (Add) {
                float2 t0 = *(const float2*)&Add[p0];
                float2 t1 = *(const float2*)&Add[p1];
                o0 += t0.x; o1 += t0.y; o2 += t1.x; o3 += t1.y;
            }
            *(float2*)&Y[p0] = make_float2(o0, o1);
            *(float2*)&Y[p1] = make_float2(o2, o3);
        }
    }
}

// ---------------- 5. VN leaky-relu (slope 0), in place over D ----------------
__global__ void lrelu_kernel(const float* __restrict__ Xnet, const float* __restrict__ P,
                             float* __restrict__ D) {
    int idx = blockIdx.x * 256 + threadIdx.x;    // over C*B_*N_
    int c = idx >> 13;
    int r = idx & 8191;
    int b = r >> 10, n = r & 1023;
    size_t base = (size_t)c*M_ + (size_t)b*3*N_ + n;
    float x0, x1, x2;
    if (P != nullptr && c >= H3) {
        int pc = (c - H3)*24 + b*3;
        x0 = P[pc]; x1 = P[pc + 1]; x2 = P[pc + 2];
    } else {
        x0 = Xnet[base]; x1 = Xnet[base + N_]; x2 = Xnet[base + 2*N_];
    }
    float d0 = D[base], d1 = D[base + N_], d2 = D[base + 2*N_];
    float dot = x0*d0 + x1*d1 + x2*d2;
    if (dot < 0.f) {
        float dd = d0*d0 + d1*d1 + d2*d2;
        float s = dot / (dd + EPSF);
        D[base]        = x0 - s*d0;
        D[base + N_]   = x1 - s*d1;
        D[base + 2*N_] = x2 - s*d2;
    } else {
        D[base] = x0; D[base + N_] = x1; D[base + 2*N_] = x2;
    }
}

// ---------------- 6. mean over points -> g_P[c][b*3+v] ----------------
__global__ void pool_kernel(const float* __restrict__ Xn) {
    int w    = blockIdx.x * 8 + (threadIdx.x >> 5);  // 0..3071 = 128*24
    int lane = threadIdx.x & 31;
    int c = w / 24; int rem = w % 24;
    size_t base = (size_t)c*M_ + (size_t)rem*N_;
    float s = 0.f;
#pragma unroll
    for (int t = 0; t < 32; t++) s += Xn[base + lane + t*32];
#pragma unroll
    for (int off = 16; off; off >>= 1) s += __shfl_xor_sync(0xffffffffu, s, off);
    if (lane == 0) g_P[c*24 + rem] = s * (1.f / N_);
}

// ---------------- 7. head: lrelu(Wd_act) + W_c ----------------
__global__ void final_kernel(const float* __restrict__ Wd, const float* __restrict__ Wc,
                             float* __restrict__ out) {
    __shared__ float s_net[H3*24];
    __shared__ float s_act[H3*24];
    int o = threadIdx.x;                     // 0..127
    for (int t = o; t < H3*24; t += 128) s_net[t] = g_P[t];
    __syncthreads();

    float dcol[24];
#pragma unroll
    for (int col = 0; col < 24; col++) dcol[col] = 0.f;
    for (int i = 0; i < H3; i++) {
        float w = Wd[o*H3 + i];
#pragma unroll
        for (int col = 0; col < 24; col++) dcol[col] += w * s_net[i*24 + col];
    }
#pragma unroll
    for (int b = 0; b < 8; b++) {
        float x0 = s_net[o*24 + b*3], x1 = s_net[o*24 + b*3 + 1], x2 = s_net[o*24 + b*3 + 2];
        float d0 = dcol[b*3], d1 = dcol[b*3 + 1], d2 = dcol[b*3 + 2];
        float dot = x0*d0 + x1*d1 + x2*d2;
        float a0 = x0, a1 = x1, a2 = x2;
        if (dot < 0.f) {
            float dd = d0*d0 + d1*d1 + d2*d2;
            float s = dot / (dd + EPSF);
            a0 = x0 - s*d0; a1 = x1 - s*d1; a2 = x2 - s*d2;
        }
        s_act[o*24 + b*3] = a0; s_act[o*24 + b*3 + 1] = a1; s_act[o*24 + b*3 + 2] = a2;
    }
    __syncthreads();

    float oc[24];
#pragma unroll
    for (int col = 0; col < 24; col++) oc[col] = 0.f;
    for (int i = 0; i < H3; i++) {
        float w = Wc[o*H3 + i];
#pragma unroll
        for (int col = 0; col < 24; col++) oc[col] += w * s_act[i*24 + col];
    }
#pragma unroll
    for (int col = 0; col < 24; col++) {
        int b = col / 3, v = col % 3;
        out[b*384 + o*3 + v] = oc[col];
    }
}

// ---------------- host ----------------
static float* symaddr(const void* sym) {
    void* p = nullptr;
    cudaGetSymbolAddress(&p, sym);
    return (float*)p;
}

extern "C" void kernel_launch(void* const* d_in, const int* in_sizes, int n_in,
                              void* d_out, int out_size) {
    const float* p      = (const float*)d_in[0];
    const float* Wpos   = (const float*)d_in[1];
    const float* Wd0s   = (const float*)d_in[2];
    const float* W0s    = (const float*)d_in[3];
    const float* Wd1s   = (const float*)d_in[4];
    const float* W1s    = (const float*)d_in[5];
    const float* Wss    = (const float*)d_in[6];
    const float* Wd_act = (const float*)d_in[7];
    const float* Wc     = (const float*)d_in[8];
    float* out = (float*)d_out;

    float* X0   = symaddr(g_X0);
    float* DS   = symaddr(g_DS);
    float* S    = DS + (size_t)C2*M_;       // rows 256..383 of DS
    float* Nt   = symaddr(g_Nt);
    float* D1   = symaddr(g_D1);
    float* Wcat = symaddr(g_Wcat);
    float* Badd = symaddr(g_Badd);

    center_kernel<<<B_, 256>>>(p);
    knn_mean_kernel<<<B_*4, 256>>>();
    featpos_kernel<<<B_*3*8, 256>>>(Wpos);
    wcat_kernel<<<(5*384*C2)/256, 256>>>(Wd0s, Wss);

    for (int i = 0; i < 5; i++) {
        const float* Wc_i = Wcat + (size_t)i*384*C2;
        const float* W0  = W0s  + (size_t)i*H3*C2;
        const float* Wd1 = Wd1s + (size_t)i*H3*H3;
        const float* W1  = W1s  + (size_t)i*H3*H3;

        if (i == 0) {
            // D;S = [Wd0; Ws] @ X0  (full K=256)
            gemm_tf32<<<dim3(384, 3), 256>>>(Wc_i, C2, X0, DS, C2, nullptr, nullptr);
        } else {
            // Badd = [Wd0;Ws][:,128:] @ P ;  D;S = [Wd0;Ws][:, :128] @ netX + Badd
            badd_kernel<<<36, 256>>>(Wc_i);
            gemm_tf32<<<dim3(384, 3), 256>>>(Wc_i, C2, X0, DS, H3, Badd, nullptr);
        }
        // D = lrelu(X, D)  (256 ch; for i>0 channels 128..255 come from P)
        lrelu_kernel<<<(C2*8192)/256, 256>>>(X0, (i == 0) ? nullptr : symaddr(g_P), DS);
        // Nt = W0 @ D  (K=256)
        gemm_tf32<<<dim3(384, 1), 256>>>(W0, C2, DS, Nt, C2, nullptr, nullptr);
        // D1 = Wd1 @ Nt  (K=128)
        gemm_tf32<<<dim3(384, 1), 256>>>(Wd1, H3, Nt, D1, H3, nullptr, nullptr);
        // D1 = lrelu(Nt, D1)  (128 ch)
        lrelu_kernel<<<(H3*8192)/256, 256>>>(Nt, nullptr, D1);
        // netX = W1 @ D1 + S  (in-place into X0 rows 0..127)
        gemm_tf32<<<dim3(384, 1), 256>>>(W1, H3, D1, X0, H3, nullptr, S);
        // P = mean over points (also the final pool when i==4)
        pool_kernel<<<384, 256>>>(X0);
    }

    final_kernel<<<1, 128>>>(Wd_act, Wc, out);
}

// round 8
// speedup vs baseline: 1.6662x; 1.0808x over previous
#include <cuda_runtime.h>
#include <cuda_bf16.h>
#include <cstdint>

#define B_   8
#define N_   1024
#define M_   24576      // B_*3*N_
#define C2   256
#define H3   128
#define KNN_ 20
#define EPSF 1e-6f

typedef __nv_bfloat16 bf16;

// ---------------- scratch (allocation-free: __device__ globals) ----------------
__device__ float g_pc[B_*N_*3];
__device__ float g_m [B_*N_*3];
__device__ bf16  g_X0h[C2*M_], g_X0l[C2*M_];     // pos feats / netX, bf16 hi/lo planes
__device__ float g_DS[384*M_];                   // gemm1 out fp32: rows 0..255 = D, 256..383 = S
__device__ bf16  g_DSh[C2*M_], g_DSl[C2*M_];     // lrelu1 out pairs
__device__ bf16  g_Nth[H3*M_], g_Ntl[H3*M_];
__device__ float g_D1[H3*M_];
__device__ bf16  g_D1h[H3*M_], g_D1l[H3*M_];
__device__ float g_P [H3*24];
__device__ float g_Wcat[5*384*C2];
__device__ float g_Badd[384*24];
__device__ bf16  g_WcatH[5*384*C2], g_WcatL[5*384*C2];
__device__ bf16  g_W0H[5*H3*C2],    g_W0L[5*H3*C2];
__device__ bf16  g_Wd1H[5*H3*H3],   g_Wd1L[5*H3*H3];
__device__ bf16  g_W1H[5*H3*H3],    g_W1L[5*H3*H3];

// ---------------- helpers ----------------
__device__ __forceinline__ void split_bf(float x, bf16& h, bf16& l) {
    h = __float2bfloat16_rn(x);
    l = __float2bfloat16_rn(x - __bfloat162float(h));
}
__device__ __forceinline__ void cp16g(void* smem, const void* g) {
    uint32_t s = (uint32_t)__cvta_generic_to_shared(smem);
    asm volatile("cp.async.cg.shared.global [%0], [%1], 16;" :: "r"(s), "l"(g));
}
__device__ __forceinline__ uint32_t scvt(const void* p) {
    return (uint32_t)__cvta_generic_to_shared(p);
}
__device__ __forceinline__ void ldsm4(uint32_t* r, uint32_t a) {
    asm volatile("ldmatrix.sync.aligned.m8n8.x4.shared.b16 {%0,%1,%2,%3}, [%4];"
        : "=r"(r[0]), "=r"(r[1]), "=r"(r[2]), "=r"(r[3]) : "r"(a));
}
__device__ __forceinline__ void ldsm4t(uint32_t* r, uint32_t a) {
    asm volatile("ldmatrix.sync.aligned.m8n8.x4.trans.shared.b16 {%0,%1,%2,%3}, [%4];"
        : "=r"(r[0]), "=r"(r[1]), "=r"(r[2]), "=r"(r[3]) : "r"(a));
}
__device__ __forceinline__ void mma16(float* c, const uint32_t* a, const uint32_t* b) {
    asm volatile("mma.sync.aligned.m16n8k16.row.col.f32.bf16.bf16.f32 "
        "{%0,%1,%2,%3}, {%4,%5,%6,%7}, {%8,%9}, {%0,%1,%2,%3};"
        : "+f"(c[0]), "+f"(c[1]), "+f"(c[2]), "+f"(c[3])
        : "r"(a[0]), "r"(a[1]), "r"(a[2]), "r"(a[3]), "r"(b[0]), "r"(b[1]));
}

// ---------------- 1. center per cloud ----------------
__global__ void center_kernel(const float* __restrict__ p) {
    int b = blockIdx.x;
    __shared__ float s[3][256];
    float s0 = 0.f, s1 = 0.f, s2 = 0.f;
    for (int n = threadIdx.x; n < N_; n += 256) {
        const float* q = p + (size_t)(b*N_ + n)*3;
        s0 += q[0]; s1 += q[1]; s2 += q[2];
    }
    s[0][threadIdx.x] = s0; s[1][threadIdx.x] = s1; s[2][threadIdx.x] = s2;
    __syncthreads();
    for (int st = 128; st > 0; st >>= 1) {
        if (threadIdx.x < st) {
            s[0][threadIdx.x] += s[0][threadIdx.x + st];
            s[1][threadIdx.x] += s[1][threadIdx.x + st];
            s[2][threadIdx.x] += s[2][threadIdx.x + st];
        }
        __syncthreads();
    }
    float m0 = s[0][0] / N_, m1 = s[1][0] / N_, m2 = s[2][0] / N_;
    for (int n = threadIdx.x; n < N_; n += 256) {
        const float* q = p + (size_t)(b*N_ + n)*3;
        float* o = g_pc + (size_t)(b*N_ + n)*3;
        o[0] = q[0] - m0; o[1] = q[1] - m1; o[2] = q[2] - m2;
    }
}

// ---------------- 2. KNN -> mean of neighbor coords ----------------
__global__ void knn_mean_kernel() {
    int b     = blockIdx.x >> 2;
    int chunk = blockIdx.x & 3;
    __shared__ float sp[N_*3];
    __shared__ float sxx[N_];
    for (int t = threadIdx.x; t < N_*3; t += 256) sp[t] = g_pc[b*N_*3 + t];
    __syncthreads();
    for (int t = threadIdx.x; t < N_; t += 256) {
        float x = sp[t*3], y = sp[t*3+1], z = sp[t*3+2];
        sxx[t] = x*x + y*y + z*z;
    }
    __syncthreads();

    int i = chunk*256 + threadIdx.x;
    float xi = sp[i*3], yi = sp[i*3+1], zi = sp[i*3+2];
    float xxi = sxx[i];

    float bd[KNN_]; int bi[KNN_];
#pragma unroll
    for (int t = 0; t < KNN_; t++) { bd[t] = -3.4e38f; bi[t] = 0; }

    for (int j = 0; j < N_; j++) {
        float dot = xi*sp[j*3] + yi*sp[j*3+1] + zi*sp[j*3+2];
        float nd  = 2.f*dot - xxi - sxx[j];
        if (nd > bd[KNN_-1]) {
            int t = KNN_-1;
            while (t > 0 && bd[t-1] < nd) { bd[t] = bd[t-1]; bi[t] = bi[t-1]; t--; }
            bd[t] = nd; bi[t] = j;
        }
    }
    float m0 = 0.f, m1 = 0.f, m2 = 0.f;
#pragma unroll
    for (int t = 0; t < KNN_; t++) {
        int j = bi[t];
        m0 += sp[j*3]; m1 += sp[j*3+1]; m2 += sp[j*3+2];
    }
    float* o = g_m + (size_t)(b*N_ + i)*3;
    o[0] = m0 / KNN_; o[1] = m1 / KNN_; o[2] = m2 / KNN_;
}

// ---------------- 3. fused edge-feature + W_pos + pool_k -> X0 hi/lo ----------------
__global__ void featpos_kernel(const float* __restrict__ Wpos) {
    int bk = blockIdx.x;                 // b(8) * v(3) * chunk(8)
    int b = bk / 24; int rem = bk % 24;
    int v = rem / 8; int chunk = rem % 8;
    int n0 = chunk * 128;
    __shared__ float f0[128], f1[128], f2[128];
    if (threadIdx.x < 128) {
        int n = n0 + threadIdx.x;
        const float* pp = g_pc + (size_t)(b*N_ + n)*3;
        const float* mm = g_m  + (size_t)(b*N_ + n)*3;
        float p0 = pp[0], p1 = pp[1], p2 = pp[2];
        float m0 = mm[0], m1 = mm[1], m2 = mm[2];
        float pv = (v == 0) ? p0 : ((v == 1) ? p1 : p2);
        float mv = (v == 0) ? m0 : ((v == 1) ? m1 : m2);
        float cv;
        if (v == 0)      cv = m1*p2 - m2*p1;
        else if (v == 1) cv = m2*p0 - m0*p2;
        else             cv = m0*p1 - m1*p0;
        f0[threadIdx.x] = mv - pv;
        f1[threadIdx.x] = pv;
        f2[threadIdx.x] = cv;
    }
    __syncthreads();
    int nl = threadIdx.x & 127;
    int oo = threadIdx.x >> 7;
    size_t colbase = (size_t)(b*3 + v)*N_ + n0;
    for (int ob = 0; ob < C2; ob += 2) {
        int o = ob + oo;
        float w0 = Wpos[o*3], w1 = Wpos[o*3+1], w2 = Wpos[o*3+2];
        float val = w0*f0[nl] + w1*f1[nl] + w2*f2[nl];
        size_t idx = (size_t)o*M_ + colbase + nl;
        bf16 h, l; split_bf(val, h, l);
        g_X0h[idx] = h; g_X0l[idx] = l;
    }
}

// ---------------- 3b. [Wd0; Ws] concat (fp32) ----------------
__global__ void wcat_kernel(const float* __restrict__ Wd0s, const float* __restrict__ Wss) {
    int idx = blockIdx.x * 256 + threadIdx.x;   // 5*384*256
    int i   = idx / (384*C2);
    int rem = idx % (384*C2);
    int r = rem / C2, c = rem % C2;
    float v = (r < C2) ? Wd0s[(size_t)i*C2*C2 + r*C2 + c]
                       : Wss [(size_t)i*H3*C2 + (r - C2)*C2 + c];
    g_Wcat[idx] = v;
}

// ---------------- 3c. fp32 -> bf16 hi/lo split ----------------
__global__ void split_kernel(const float* __restrict__ src, bf16* __restrict__ h,
                             bf16* __restrict__ l) {
    int idx = blockIdx.x * 256 + threadIdx.x;
    bf16 hh, ll; split_bf(src[idx], hh, ll);
    h[idx] = hh; l[idx] = ll;
}

// ---------------- 3d. Badd[384][24] = Wcat[:,128:] @ P ----------------
__global__ void badd_kernel(const float* __restrict__ Wcat) {
    int idx = blockIdx.x * 256 + threadIdx.x;   // 9216
    if (idx >= 384*24) return;
    int r = idx / 24, cg = idx % 24;
    float s = 0.f;
#pragma unroll 8
    for (int k = 0; k < H3; k++)
        s += Wcat[r*C2 + H3 + k] * g_P[k*24 + cg];
    g_Badd[idx] = s;
}

// ---------------- 4. bf16x4 tensor-core GEMM: Y = A @ B ----------------
// block tile 128(M) x 64(N), BK=16, 8 warps (4x2), warp tile 32x32
__global__ __launch_bounds__(256, 2)
void gemm_bfx4_kernel(const bf16* __restrict__ Ah, const bf16* __restrict__ Al, int lda,
                      const bf16* __restrict__ Bh, const bf16* __restrict__ Bl,
                      float* __restrict__ Yf, bf16* __restrict__ Yh, bf16* __restrict__ Yl,
                      int K, const float* __restrict__ Badd, const float* __restrict__ Add)
{
    const int SA = 24, SB = 72;                  // padded bf16 strides (48B / 144B)
    __shared__ bf16 sAh[2][128*SA], sAl[2][128*SA];
    __shared__ bf16 sBh[2][16*SB],  sBl[2][16*SB];
    int tid = threadIdx.x, lane = tid & 31, wid = tid >> 5;
    int warp_m = wid >> 1, warp_n = wid & 1;
    int gid = lane >> 2, tig = lane & 3;
    int nBase = blockIdx.x * 64, oBase = blockIdx.y * 128;

    // loaders
    int aRow = tid >> 1, aSeg = (tid & 1) * 8;
    int bRow = (tid & 127) >> 3, bSeg = (tid & 7) * 8;
    const bf16* Agh = Ah + (size_t)(oBase + aRow)*lda + aSeg;
    const bf16* Agl = Al + (size_t)(oBase + aRow)*lda + aSeg;
    const bool bHi = (tid < 128);
    const bf16* Bg = (bHi ? Bh : Bl) + (size_t)bRow*M_ + nBase + bSeg;
    int bOffSm = bRow*SB + bSeg;

    // ldmatrix lane offsets (bytes)
    int selA = ((lane >> 3) & 1) * 8 + (lane & 7);
    int selAk = (lane >> 4) * 8;
    uint32_t aOff[2];
#pragma unroll
    for (int mt = 0; mt < 2; mt++)
        aOff[mt] = (uint32_t)(((warp_m*32 + mt*16 + selA)*SA + selAk) * 2);
    int selBk = ((lane >> 3) & 1) * 8 + (lane & 7);
    int selBn = (lane >> 4) * 8;
    uint32_t bOff[2];
#pragma unroll
    for (int nt2 = 0; nt2 < 2; nt2++)
        bOff[nt2] = (uint32_t)((selBk*SB + warp_n*32 + nt2*16 + selBn) * 2);

    uint32_t sAhB[2] = { scvt(sAh[0]), scvt(sAh[1]) };
    uint32_t sAlB[2] = { scvt(sAl[0]), scvt(sAl[1]) };
    uint32_t sBhB[2] = { scvt(sBh[0]), scvt(sBh[1]) };
    uint32_t sBlB[2] = { scvt(sBl[0]), scvt(sBl[1]) };

    int stages = K >> 4;
    float c[2][4][4];
#pragma unroll
    for (int mt = 0; mt < 2; mt++)
#pragma unroll
        for (int nt = 0; nt < 4; nt++)
#pragma unroll
            for (int r = 0; r < 4; r++) c[mt][nt][r] = 0.f;

#define LOAD_STAGE(s, buf)                                              \
    do {                                                                \
        int k0_ = (s) * 16;                                             \
        cp16g(&sAh[buf][aRow*SA + aSeg], Agh + k0_);                    \
        cp16g(&sAl[buf][aRow*SA + aSeg], Agl + k0_);                    \
        cp16g((bHi ? &sBh[buf][bOffSm] : &sBl[buf][bOffSm]),            \
              Bg + (size_t)k0_*M_);                                     \
        asm volatile("cp.async.commit_group;");                         \
    } while (0)

    LOAD_STAGE(0, 0);
    if (stages > 1) LOAD_STAGE(1, 1);

    for (int s = 0; s < stages; s++) {
        if (s == stages - 1) asm volatile("cp.async.wait_group 0;");
        else                 asm volatile("cp.async.wait_group 1;");
        __syncthreads();
        int buf = s & 1;

        uint32_t ah[2][4], al[2][4], bh[2][4], bl[2][4];
        ldsm4(ah[0], sAhB[buf] + aOff[0]);
        ldsm4(ah[1], sAhB[buf] + aOff[1]);
        ldsm4(al[0], sAlB[buf] + aOff[0]);
        ldsm4(al[1], sAlB[buf] + aOff[1]);
        ldsm4t(bh[0], sBhB[buf] + bOff[0]);
        ldsm4t(bh[1], sBhB[buf] + bOff[1]);
        ldsm4t(bl[0], sBlB[buf] + bOff[0]);
        ldsm4t(bl[1], sBlB[buf] + bOff[1]);

#pragma unroll
        for (int mt = 0; mt < 2; mt++)
#pragma unroll
            for (int nt = 0; nt < 4; nt++) {
                const uint32_t* bhf = &bh[nt >> 1][(nt & 1)*2];
                const uint32_t* blf = &bl[nt >> 1][(nt & 1)*2];
                float* cc = c[mt][nt];
                mma16(cc, al[mt], blf);   // lo*lo
                mma16(cc, ah[mt], blf);   // hi*lo
                mma16(cc, al[mt], bhf);   // lo*hi
                mma16(cc, ah[mt], bhf);   // hi*hi
            }
        __syncthreads();
        if (s + 2 < stages) LOAD_STAGE(s + 2, buf);
    }
#undef LOAD_STAGE

    int cg = nBase >> 10;   // column group (b*3+v); tile never straddles groups
#pragma unroll
    for (int mt = 0; mt < 2; mt++) {
#pragma unroll
        for (int nt = 0; nt < 4; nt++) {
            int r0 = oBase + warp_m*32 + mt*16 + gid;
            int r1 = r0 + 8;
            int col = nBase + warp_n*32 + nt*8 + tig*2;
            float* cc = c[mt][nt];
            float ba0 = 0.f, ba1 = 0.f;
            if (Badd) { ba0 = Badd[r0*24 + cg]; ba1 = Badd[r1*24 + cg]; }
            size_t p0 = (size_t)r0*M_ + col;
            size_t p1 = (size_t)r1*M_ + col;
            float o0 = cc[0] + ba0, o1 = cc[1] + ba0;
            float o2 = cc[2] + ba1, o3 = cc[3] + ba1;
            if (Add) {
                float2 t0 = *(const float2*)&Add[p0];
                float2 t1 = *(const float2*)&Add[p1];
                o0 += t0.x; o1 += t0.y; o2 += t1.x; o3 += t1.y;
            }
            if (Yf) {
                *(float2*)&Yf[p0] = make_float2(o0, o1);
                *(float2*)&Yf[p1] = make_float2(o2, o3);
            } else {
                __nv_bfloat162 h0, l0, h1, l1;
                split_bf(o0, h0.x, l0.x); split_bf(o1, h0.y, l0.y);
                split_bf(o2, h1.x, l1.x); split_bf(o3, h1.y, l1.y);
                *(__nv_bfloat162*)&Yh[p0] = h0;
                *(__nv_bfloat162*)&Yl[p0] = l0;
                *(__nv_bfloat162*)&Yh[p1] = h1;
                *(__nv_bfloat162*)&Yl[p1] = l1;
            }
        }
    }
}

// ---------------- 5. VN leaky-relu: x from pairs (or P), d from fp32; out pairs --------
__global__ void lrelu_kernel(const bf16* __restrict__ Xh, const bf16* __restrict__ Xl,
                             const float* __restrict__ P, const float* __restrict__ Dsrc,
                             bf16* __restrict__ Dh, bf16* __restrict__ Dl) {
    int idx = blockIdx.x * 256 + threadIdx.x;
    int c = idx >> 13;
    int r = idx & 8191;
    int b = r >> 10, n = r & 1023;
    size_t base = (size_t)c*M_ + (size_t)b*3*N_ + n;
    float x0, x1, x2;
    if (P != nullptr && c >= H3) {
        int pc = (c - H3)*24 + b*3;
        x0 = P[pc]; x1 = P[pc + 1]; x2 = P[pc + 2];
    } else {
        x0 = __bfloat162float(Xh[base])        + __bfloat162float(Xl[base]);
        x1 = __bfloat162float(Xh[base + N_])   + __bfloat162float(Xl[base + N_]);
        x2 = __bfloat162float(Xh[base + 2*N_]) + __bfloat162float(Xl[base + 2*N_]);
    }
    float d0 = Dsrc[base], d1 = Dsrc[base + N_], d2 = Dsrc[base + 2*N_];
    float o0 = x0, o1 = x1, o2 = x2;
    float dot = x0*d0 + x1*d1 + x2*d2;
    if (dot < 0.f) {
        float dd = d0*d0 + d1*d1 + d2*d2;
        float s = dot / (dd + EPSF);
        o0 = x0 - s*d0; o1 = x1 - s*d1; o2 = x2 - s*d2;
    }
    bf16 h, l;
    split_bf(o0, h, l); Dh[base]        = h; Dl[base]        = l;
    split_bf(o1, h, l); Dh[base + N_]   = h; Dl[base + N_]   = l;
    split_bf(o2, h, l); Dh[base + 2*N_] = h; Dl[base + 2*N_] = l;
}

// ---------------- 6. mean over points (from pairs) -> g_P ----------------
__global__ void pool_kernel(const bf16* __restrict__ Xh, const bf16* __restrict__ Xl) {
    int w    = blockIdx.x * 8 + (threadIdx.x >> 5);  // 128*24 warps
    int lane = threadIdx.x & 31;
    int c = w / 24; int rem = w % 24;
    size_t base = (size_t)c*M_ + (size_t)rem*N_;
    float s = 0.f;
#pragma unroll
    for (int t = 0; t < 32; t++) {
        size_t q = base + lane + t*32;
        s += __bfloat162float(Xh[q]) + __bfloat162float(Xl[q]);
    }
#pragma unroll
    for (int off = 16; off; off >>= 1) s += __shfl_xor_sync(0xffffffffu, s, off);
    if (lane == 0) g_P[c*24 + rem] = s * (1.f / N_);
}

// ---------------- 7. head ----------------
__global__ void final_kernel(const float* __restrict__ Wd, const float* __restrict__ Wc,
                             float* __restrict__ out) {
    __shared__ float s_net[H3*24];
    __shared__ float s_act[H3*24];
    int o = threadIdx.x;
    for (int t = o; t < H3*24; t += 128) s_net[t] = g_P[t];
    __syncthreads();

    float dcol[24];
#pragma unroll
    for (int col = 0; col < 24; col++) dcol[col] = 0.f;
    for (int i = 0; i < H3; i++) {
        float w = Wd[o*H3 + i];
#pragma unroll
        for (int col = 0; col < 24; col++) dcol[col] += w * s_net[i*24 + col];
    }
#pragma unroll
    for (int b = 0; b < 8; b++) {
        float x0 = s_net[o*24 + b*3], x1 = s_net[o*24 + b*3 + 1], x2 = s_net[o*24 + b*3 + 2];
        float d0 = dcol[b*3], d1 = dcol[b*3 + 1], d2 = dcol[b*3 + 2];
        float dot = x0*d0 + x1*d1 + x2*d2;
        float a0 = x0, a1 = x1, a2 = x2;
        if (dot < 0.f) {
            float dd = d0*d0 + d1*d1 + d2*d2;
            float s = dot / (dd + EPSF);
            a0 = x0 - s*d0; a1 = x1 - s*d1; a2 = x2 - s*d2;
        }
        s_act[o*24 + b*3] = a0; s_act[o*24 + b*3 + 1] = a1; s_act[o*24 + b*3 + 2] = a2;
    }
    __syncthreads();

    float oc[24];
#pragma unroll
    for (int col = 0; col < 24; col++) oc[col] = 0.f;
    for (int i = 0; i < H3; i++) {
        float w = Wc[o*H3 + i];
#pragma unroll
        for (int col = 0; col < 24; col++) oc[col] += w * s_act[i*24 + col];
    }
#pragma unroll
    for (int col = 0; col < 24; col++) {
        int b = col / 3, v = col % 3;
        out[b*384 + o*3 + v] = oc[col];
    }
}

// ---------------- host ----------------
static float* symaddrf(const void* sym) {
    void* p = nullptr; cudaGetSymbolAddress(&p, sym); return (float*)p;
}
static bf16* symaddrb(const void* sym) {
    void* p = nullptr; cudaGetSymbolAddress(&p, sym); return (bf16*)p;
}

extern "C" void kernel_launch(void* const* d_in, const int* in_sizes, int n_in,
                              void* d_out, int out_size) {
    const float* p      = (const float*)d_in[0];
    const float* Wpos   = (const float*)d_in[1];
    const float* Wd0s   = (const float*)d_in[2];
    const float* W0s    = (const float*)d_in[3];
    const float* Wd1s   = (const float*)d_in[4];
    const float* W1s    = (const float*)d_in[5];
    const float* Wss    = (const float*)d_in[6];
    const float* Wd_act = (const float*)d_in[7];
    const float* Wc     = (const float*)d_in[8];
    float* out = (float*)d_out;

    float* DS    = symaddrf(g_DS);
    float* S     = DS + (size_t)C2*M_;
    float* D1    = symaddrf(g_D1);
    float* Wcat  = symaddrf(g_Wcat);
    float* Badd  = symaddrf(g_Badd);
    float* P     = symaddrf(g_P);
    bf16 *X0h = symaddrb(g_X0h), *X0l = symaddrb(g_X0l);
    bf16 *DSh = symaddrb(g_DSh), *DSl = symaddrb(g_DSl);
    bf16 *Nth = symaddrb(g_Nth), *Ntl = symaddrb(g_Ntl);
    bf16 *D1h = symaddrb(g_D1h), *D1l = symaddrb(g_D1l);
    bf16 *WcH = symaddrb(g_WcatH), *WcL = symaddrb(g_WcatL);
    bf16 *W0H = symaddrb(g_W0H),   *W0L = symaddrb(g_W0L);
    bf16 *Wd1H = symaddrb(g_Wd1H), *Wd1L = symaddrb(g_Wd1L);
    bf16 *W1H = symaddrb(g_W1H),   *W1L = symaddrb(g_W1L);

    center_kernel<<<B_, 256>>>(p);
    knn_mean_kernel<<<B_*4, 256>>>();
    featpos_kernel<<<B_*3*8, 256>>>(Wpos);
    wcat_kernel<<<(5*384*C2)/256, 256>>>(Wd0s, Wss);
    split_kernel<<<(5*384*C2)/256, 256>>>(Wcat, WcH, WcL);
    split_kernel<<<(5*H3*C2)/256, 256>>>(W0s, W0H, W0L);
    split_kernel<<<(5*H3*H3)/256, 256>>>(Wd1s, Wd1H, Wd1L);
    split_kernel<<<(5*H3*H3)/256, 256>>>(W1s, W1H, W1L);

    for (int i = 0; i < 5; i++) {
        size_t oc2 = (size_t)i*384*C2;
        const bf16* WciH = WcH + oc2; const bf16* WciL = WcL + oc2;
        const bf16* W0iH = W0H + (size_t)i*H3*C2;  const bf16* W0iL = W0L + (size_t)i*H3*C2;
        const bf16* Wd1iH = Wd1H + (size_t)i*H3*H3; const bf16* Wd1iL = Wd1L + (size_t)i*H3*H3;
        const bf16* W1iH = W1H + (size_t)i*H3*H3;  const bf16* W1iL = W1L + (size_t)i*H3*H3;

        if (i == 0) {
            gemm_bfx4_kernel<<<dim3(384, 3), 256>>>(WciH, WciL, C2, X0h, X0l,
                                                    DS, nullptr, nullptr, C2, nullptr, nullptr);
        } else {
            badd_kernel<<<36, 256>>>(Wcat + oc2);
            gemm_bfx4_kernel<<<dim3(384, 3), 256>>>(WciH, WciL, C2, X0h, X0l,
                                                    DS, nullptr, nullptr, H3, Badd, nullptr);
        }
        // D' = lrelu(X, D) -> pairs (256 ch; for i>0 channels 128..255 x comes from P)
        lrelu_kernel<<<(C2*8192)/256, 256>>>(X0h, X0l, (i == 0) ? nullptr : P, DS, DSh, DSl);
        // Nt = W0 @ D'  (K=256) -> pairs
        gemm_bfx4_kernel<<<dim3(384, 1), 256>>>(W0iH, W0iL, C2, DSh, DSl,
                                                nullptr, Nth, Ntl, C2, nullptr, nullptr);
        // D1 = Wd1 @ Nt (K=128) -> fp32
        gemm_bfx4_kernel<<<dim3(384, 1), 256>>>(Wd1iH, Wd1iL, H3, Nth, Ntl,
                                                D1, nullptr, nullptr, H3, nullptr, nullptr);
        // D1' = lrelu(Nt, D1) -> pairs (128 ch)
        lrelu_kernel<<<(H3*8192)/256, 256>>>(Nth, Ntl, nullptr, D1, D1h, D1l);
        // netX = W1 @ D1' + S (K=128) -> pairs, in place into X0 rows 0..127
        gemm_bfx4_kernel<<<dim3(384, 1), 256>>>(W1iH, W1iL, H3, D1h, D1l,
                                                nullptr, X0h, X0l, H3, nullptr, S);
        // P = mean over points
        pool_kernel<<<384, 256>>>(X0h, X0l);
    }

    final_kernel<<<1, 128>>>(Wd_act, Wc, out);
}

// round 10
// speedup vs baseline: 1.6756x; 1.0056x over previous
#include <cuda_runtime.h>
#include <cuda_bf16.h>
#include <cstdint>

#define B_   8
#define N_   1024
#define M_   24576      // B_*3*N_
#define C2   256
#define H3   128
#define KNN_ 20
#define EPSF 1e-6f

typedef __nv_bfloat16 bf16;

// ---------------- scratch (allocation-free: __device__ globals) ----------------
__device__ float g_pc[B_*N_*3];
__device__ float g_m [B_*N_*3];
__device__ bf16  g_X0h[C2*M_], g_X0l[C2*M_];     // pos feats / netX, bf16 hi/lo planes
__device__ float g_DS[384*M_];                   // gemm1 out fp32: rows 0..255 = D, 256..383 = S
__device__ bf16  g_DSh[C2*M_], g_DSl[C2*M_];     // lrelu1 out pairs
__device__ bf16  g_Nth[H3*M_], g_Ntl[H3*M_];
__device__ float g_D1[H3*M_];
__device__ bf16  g_D1h[H3*M_], g_D1l[H3*M_];
__device__ float g_P [H3*24];
__device__ float g_Wcat[5*384*C2];
__device__ float g_Badd[384*24];
__device__ bf16  g_WcatH[5*384*C2], g_WcatL[5*384*C2];
__device__ bf16  g_W0H[5*H3*C2],    g_W0L[5*H3*C2];
__device__ bf16  g_Wd1H[5*H3*H3],   g_Wd1L[5*H3*H3];
__device__ bf16  g_W1H[5*H3*H3],    g_W1L[5*H3*H3];

// ---------------- helpers ----------------
__device__ __forceinline__ void split_bf(float x, bf16& h, bf16& l) {
    h = __float2bfloat16_rn(x);
    l = __float2bfloat16_rn(x - __bfloat162float(h));
}
__device__ __forceinline__ void cp16g(void* smem, const void* g) {
    uint32_t s = (uint32_t)__cvta_generic_to_shared(smem);
    asm volatile("cp.async.cg.shared.global [%0], [%1], 16;" :: "r"(s), "l"(g));
}
__device__ __forceinline__ uint32_t scvt(const void* p) {
    return (uint32_t)__cvta_generic_to_shared(p);
}
__device__ __forceinline__ void ldsm4(uint32_t* r, uint32_t a) {
    asm volatile("ldmatrix.sync.aligned.m8n8.x4.shared.b16 {%0,%1,%2,%3}, [%4];"
        : "=r"(r[0]), "=r"(r[1]), "=r"(r[2]), "=r"(r[3]) : "r"(a));
}
__device__ __forceinline__ void ldsm4t(uint32_t* r, uint32_t a) {
    asm volatile("ldmatrix.sync.aligned.m8n8.x4.trans.shared.b16 {%0,%1,%2,%3}, [%4];"
        : "=r"(r[0]), "=r"(r[1]), "=r"(r[2]), "=r"(r[3]) : "r"(a));
}
__device__ __forceinline__ void mma16(float* c, const uint32_t* a, const uint32_t* b) {
    asm volatile("mma.sync.aligned.m16n8k16.row.col.f32.bf16.bf16.f32 "
        "{%0,%1,%2,%3}, {%4,%5,%6,%7}, {%8,%9}, {%0,%1,%2,%3};"
        : "+f"(c[0]), "+f"(c[1]), "+f"(c[2]), "+f"(c[3])
        : "r"(a[0]), "r"(a[1]), "r"(a[2]), "r"(a[3]), "r"(b[0]), "r"(b[1]));
}

// ---------------- 1. center per cloud ----------------
__global__ void center_kernel(const float* __restrict__ p) {
    int b = blockIdx.x;
    __shared__ float s[3][256];
    float s0 = 0.f, s1 = 0.f, s2 = 0.f;
    for (int n = threadIdx.x; n < N_; n += 256) {
        const float* q = p + (size_t)(b*N_ + n)*3;
        s0 += q[0]; s1 += q[1]; s2 += q[2];
    }
    s[0][threadIdx.x] = s0; s[1][threadIdx.x] = s1; s[2][threadIdx.x] = s2;
    __syncthreads();
    for (int st = 128; st > 0; st >>= 1) {
        if (threadIdx.x < st) {
            s[0][threadIdx.x] += s[0][threadIdx.x + st];
            s[1][threadIdx.x] += s[1][threadIdx.x + st];
            s[2][threadIdx.x] += s[2][threadIdx.x + st];
        }
        __syncthreads();
    }
    float m0 = s[0][0] / N_, m1 = s[1][0] / N_, m2 = s[2][0] / N_;
    for (int n = threadIdx.x; n < N_; n += 256) {
        const float* q = p + (size_t)(b*N_ + n)*3;
        float* o = g_pc + (size_t)(b*N_ + n)*3;
        o[0] = q[0] - m0; o[1] = q[1] - m1; o[2] = q[2] - m2;
    }
}

// ---------------- 2. KNN -> mean of neighbor coords ----------------
__global__ void knn_mean_kernel() {
    int b     = blockIdx.x >> 2;
    int chunk = blockIdx.x & 3;
    __shared__ float sp[N_*3];
    __shared__ float sxx[N_];
    for (int t = threadIdx.x; t < N_*3; t += 256) sp[t] = g_pc[b*N_*3 + t];
    __syncthreads();
    for (int t = threadIdx.x; t < N_; t += 256) {
        float x = sp[t*3], y = sp[t*3+1], z = sp[t*3+2];
        sxx[t] = x*x + y*y + z*z;
    }
    __syncthreads();

    int i = chunk*256 + threadIdx.x;
    float xi = sp[i*3], yi = sp[i*3+1], zi = sp[i*3+2];
    float xxi = sxx[i];

    float bd[KNN_]; int bi[KNN_];
#pragma unroll
    for (int t = 0; t < KNN_; t++) { bd[t] = -3.4e38f; bi[t] = 0; }

    for (int j = 0; j < N_; j++) {
        float dot = xi*sp[j*3] + yi*sp[j*3+1] + zi*sp[j*3+2];
        float nd  = 2.f*dot - xxi - sxx[j];
        if (nd > bd[KNN_-1]) {
            int t = KNN_-1;
            while (t > 0 && bd[t-1] < nd) { bd[t] = bd[t-1]; bi[t] = bi[t-1]; t--; }
            bd[t] = nd; bi[t] = j;
        }
    }
    float m0 = 0.f, m1 = 0.f, m2 = 0.f;
#pragma unroll
    for (int t = 0; t < KNN_; t++) {
        int j = bi[t];
        m0 += sp[j*3]; m1 += sp[j*3+1]; m2 += sp[j*3+2];
    }
    float* o = g_m + (size_t)(b*N_ + i)*3;
    o[0] = m0 / KNN_; o[1] = m1 / KNN_; o[2] = m2 / KNN_;
}

// ---------------- 3. fused edge-feature + W_pos + pool_k -> X0 hi/lo ----------------
__global__ void featpos_kernel(const float* __restrict__ Wpos) {
    int bk = blockIdx.x;                 // b(8) * v(3) * chunk(8)
    int b = bk / 24; int rem = bk % 24;
    int v = rem / 8; int chunk = rem % 8;
    int n0 = chunk * 128;
    __shared__ float f0[128], f1[128], f2[128];
    if (threadIdx.x < 128) {
        int n = n0 + threadIdx.x;
        const float* pp = g_pc + (size_t)(b*N_ + n)*3;
        const float* mm = g_m  + (size_t)(b*N_ + n)*3;
        float p0 = pp[0], p1 = pp[1], p2 = pp[2];
        float m0 = mm[0], m1 = mm[1], m2 = mm[2];
        float pv = (v == 0) ? p0 : ((v == 1) ? p1 : p2);
        float mv = (v == 0) ? m0 : ((v == 1) ? m1 : m2);
        float cv;
        if (v == 0)      cv = m1*p2 - m2*p1;
        else if (v == 1) cv = m2*p0 - m0*p2;
        else             cv = m0*p1 - m1*p0;
        f0[threadIdx.x] = mv - pv;
        f1[threadIdx.x] = pv;
        f2[threadIdx.x] = cv;
    }
    __syncthreads();
    int nl = threadIdx.x & 127;
    int oo = threadIdx.x >> 7;
    size_t colbase = (size_t)(b*3 + v)*N_ + n0;
    for (int ob = 0; ob < C2; ob += 2) {
        int o = ob + oo;
        float w0 = Wpos[o*3], w1 = Wpos[o*3+1], w2 = Wpos[o*3+2];
        float val = w0*f0[nl] + w1*f1[nl] + w2*f2[nl];
        size_t idx = (size_t)o*M_ + colbase + nl;
        bf16 h, l; split_bf(val, h, l);
        g_X0h[idx] = h; g_X0l[idx] = l;
    }
}

// ---------------- 3b. [Wd0; Ws] concat -> fp32 + bf16 pairs (one pass) ----------------
__global__ void wsplit_kernel(const float* __restrict__ Wd0s, const float* __restrict__ Wss) {
    int idx = blockIdx.x * 256 + threadIdx.x;   // 5*384*256
    int i   = idx / (384*C2);
    int rem = idx % (384*C2);
    int r = rem / C2, c = rem % C2;
    float v = (r < C2) ? Wd0s[(size_t)i*C2*C2 + r*C2 + c]
                       : Wss [(size_t)i*H3*C2 + (r - C2)*C2 + c];
    g_Wcat[idx] = v;
    bf16 h, l; split_bf(v, h, l);
    g_WcatH[idx] = h; g_WcatL[idx] = l;
}

// ---------------- 3c. split W0/Wd1/W1 in one launch ----------------
__global__ void splitall_kernel(const float* __restrict__ W0s,
                                const float* __restrict__ Wd1s,
                                const float* __restrict__ W1s) {
    int idx = blockIdx.x * 256 + threadIdx.x;
    const int n0 = 5*H3*C2;            // 163840
    const int n1 = n0 + 5*H3*H3;       // 245760
    bf16 h, l;
    if (idx < n0) {
        split_bf(W0s[idx], h, l);  g_W0H[idx] = h;  g_W0L[idx] = l;
    } else if (idx < n1) {
        int j = idx - n0;
        split_bf(Wd1s[j], h, l);   g_Wd1H[j] = h;   g_Wd1L[j] = l;
    } else {
        int j = idx - n1;
        split_bf(W1s[j], h, l);    g_W1H[j] = h;    g_W1L[j] = l;
    }
}

// ---------------- 3d. Badd[384][24] = Wcat[:,128:] @ P ----------------
__global__ void badd_kernel(const float* __restrict__ Wcat) {
    int idx = blockIdx.x * 256 + threadIdx.x;   // 9216
    if (idx >= 384*24) return;
    int r = idx / 24, cg = idx % 24;
    float s = 0.f;
#pragma unroll 8
    for (int k = 0; k < H3; k++)
        s += Wcat[r*C2 + H3 + k] * g_P[k*24 + cg];
    g_Badd[idx] = s;
}

// ---------------- 4. bf16x3 tensor-core GEMM: Y = A @ B ----------------
// block tile 128(M) x 64(N), BK=16, 3-stage cp.async pipeline, 8 warps (4x2)
// A smem: stride 16 elements (32B) with 16B-granule XOR swizzle:
//   elem_off(row, g) = row*16 + ((g ^ ((row>>2)&1)) << 3)   -- cp.async dest 16B-aligned,
//   ldmatrix phases conflict-free.
// 3-term compensation: ah*bh + ah*bl + al*bh  (lo*lo dropped: ~4e-6 relative)
// Optional fused point-mean pool into Psum (atomicAdd, pre-zeroed).
__global__ __launch_bounds__(256, 2)
void gemm_bfx3_kernel(const bf16* __restrict__ Ah, const bf16* __restrict__ Al, int lda,
                      const bf16* __restrict__ Bh, const bf16* __restrict__ Bl,
                      float* __restrict__ Yf, bf16* __restrict__ Yh, bf16* __restrict__ Yl,
                      int K, const float* __restrict__ Badd, const float* __restrict__ Add,
                      float* __restrict__ Psum)
{
    const int SA = 16, SB = 72;        // A: 32B stride + swizzle; B: 144B padded stride
    __shared__ bf16 sAh[3][128*SA], sAl[3][128*SA];
    __shared__ bf16 sBh[3][16*SB],  sBl[3][16*SB];
    int tid = threadIdx.x, lane = tid & 31, wid = tid >> 5;
    int warp_m = wid >> 1, warp_n = wid & 1;
    int gid = lane >> 2, tig = lane & 3;
    int nBase = blockIdx.x * 64, oBase = blockIdx.y * 128;

    // loaders
    int aRow = tid >> 1, aG = tid & 1;
    int bRow = (tid & 127) >> 3, bSeg = (tid & 7) * 8;
    const bf16* Agh = Ah + (size_t)(oBase + aRow)*lda + aG*8;
    const bf16* Agl = Al + (size_t)(oBase + aRow)*lda + aG*8;
    const bool bHi = (tid < 128);
    const bf16* Bg = (bHi ? Bh : Bl) + (size_t)bRow*M_ + nBase + bSeg;
    int aOffSm = aRow*SA + ((aG ^ ((aRow >> 2) & 1)) << 3);   // swizzled dest (elements)
    int bOffSm = bRow*SB + bSeg;

    // ldmatrix lane offsets (bytes)
    int selA = ((lane >> 3) & 1) * 8 + (lane & 7);   // row within 16
    int halfA = lane >> 4;                           // k-half (0/1)
    uint32_t aOff[2];
#pragma unroll
    for (int mt = 0; mt < 2; mt++) {
        int row = warp_m*32 + mt*16 + selA;
        aOff[mt] = (uint32_t)((row*SA + ((halfA ^ ((row >> 2) & 1)) << 3)) * 2);
    }
    int selBk = ((lane >> 3) & 1) * 8 + (lane & 7);
    int selBn = (lane >> 4) * 8;
    uint32_t bOff[2];
#pragma unroll
    for (int nt2 = 0; nt2 < 2; nt2++)
        bOff[nt2] = (uint32_t)((selBk*SB + warp_n*32 + nt2*16 + selBn) * 2);

    uint32_t sAhB[3] = { scvt(sAh[0]), scvt(sAh[1]), scvt(sAh[2]) };
    uint32_t sAlB[3] = { scvt(sAl[0]), scvt(sAl[1]), scvt(sAl[2]) };
    uint32_t sBhB[3] = { scvt(sBh[0]), scvt(sBh[1]), scvt(sBh[2]) };
    uint32_t sBlB[3] = { scvt(sBl[0]), scvt(sBl[1]), scvt(sBl[2]) };

    int stages = K >> 4;
    float c[2][4][4];
#pragma unroll
    for (int mt = 0; mt < 2; mt++)
#pragma unroll
        for (int nt = 0; nt < 4; nt++)
#pragma unroll
            for (int r = 0; r < 4; r++) c[mt][nt][r] = 0.f;

#define LOAD_STAGE(s, buf)                                              \
    do {                                                                \
        int k0_ = (s) * 16;                                             \
        cp16g(&sAh[buf][aOffSm], Agh + k0_);                            \
        cp16g(&sAl[buf][aOffSm], Agl + k0_);                            \
        cp16g((bHi ? &sBh[buf][bOffSm] : &sBl[buf][bOffSm]),            \
              Bg + (size_t)k0_*M_);                                     \
        asm volatile("cp.async.commit_group;");                         \
    } while (0)

    LOAD_STAGE(0, 0);
    LOAD_STAGE(1, 1);

    for (int s = 0; s < stages; s++) {
        if (s == stages - 1) asm volatile("cp.async.wait_group 0;");
        else                 asm volatile("cp.async.wait_group 1;");
        __syncthreads();
        int buf = s % 3;
        if (s + 2 < stages) LOAD_STAGE(s + 2, (s + 2) % 3);

        uint32_t ah[2][4], al[2][4], bh[2][4], bl[2][4];
        ldsm4(ah[0], sAhB[buf] + aOff[0]);
        ldsm4(ah[1], sAhB[buf] + aOff[1]);
        ldsm4(al[0], sAlB[buf] + aOff[0]);
        ldsm4(al[1], sAlB[buf] + aOff[1]);
        ldsm4t(bh[0], sBhB[buf] + bOff[0]);
        ldsm4t(bh[1], sBhB[buf] + bOff[1]);
        ldsm4t(bl[0], sBlB[buf] + bOff[0]);
        ldsm4t(bl[1], sBlB[buf] + bOff[1]);

#pragma unroll
        for (int mt = 0; mt < 2; mt++)
#pragma unroll
            for (int nt = 0; nt < 4; nt++) {
                const uint32_t* bhf = &bh[nt >> 1][(nt & 1)*2];
                const uint32_t* blf = &bl[nt >> 1][(nt & 1)*2];
                float* cc = c[mt][nt];
                mma16(cc, ah[mt], bhf);   // hi*hi
                mma16(cc, ah[mt], blf);   // hi*lo
                mma16(cc, al[mt], bhf);   // lo*hi
            }
    }
#undef LOAD_STAGE

    int cg = nBase >> 10;   // column group (b*3+v); tile never straddles groups
    float ps0[2] = {0.f, 0.f}, ps1[2] = {0.f, 0.f};
#pragma unroll
    for (int mt = 0; mt < 2; mt++) {
#pragma unroll
        for (int nt = 0; nt < 4; nt++) {
            int r0 = oBase + warp_m*32 + mt*16 + gid;
            int r1 = r0 + 8;
            int col = nBase + warp_n*32 + nt*8 + tig*2;
            float* cc = c[mt][nt];
            float ba0 = 0.f, ba1 = 0.f;
            if (Badd) { ba0 = Badd[r0*24 + cg]; ba1 = Badd[r1*24 + cg]; }
            size_t p0 = (size_t)r0*M_ + col;
            size_t p1 = (size_t)r1*M_ + col;
            float o0 = cc[0] + ba0, o1 = cc[1] + ba0;
            float o2 = cc[2] + ba1, o3 = cc[3] + ba1;
            if (Add) {
                float2 t0 = *(const float2*)&Add[p0];
                float2 t1 = *(const float2*)&Add[p1];
                o0 += t0.x; o1 += t0.y; o2 += t1.x; o3 += t1.y;
            }
            ps0[mt] += o0 + o1;
            ps1[mt] += o2 + o3;
            if (Yf) {
                *(float2*)&Yf[p0] = make_float2(o0, o1);
                *(float2*)&Yf[p1] = make_float2(o2, o3);
            } else {
                __nv_bfloat162 h0, l0, h1, l1;
                split_bf(o0, h0.x, l0.x); split_bf(o1, h0.y, l0.y);
                split_bf(o2, h1.x, l1.x); split_bf(o3, h1.y, l1.y);
                *(__nv_bfloat162*)&Yh[p0] = h0;
                *(__nv_bfloat162*)&Yl[p0] = l0;
                *(__nv_bfloat162*)&Yh[p1] = h1;
                *(__nv_bfloat162*)&Yl[p1] = l1;
            }
        }
    }
    if (Psum) {
        const float invN = 1.f / N_;
#pragma unroll
        for (int mt = 0; mt < 2; mt++) {
            float a = ps0[mt], b2 = ps1[mt];
            a  += __shfl_xor_sync(0xffffffffu, a, 1);
            a  += __shfl_xor_sync(0xffffffffu, a, 2);
            b2 += __shfl_xor_sync(0xffffffffu, b2, 1);
            b2 += __shfl_xor_sync(0xffffffffu, b2, 2);
            if (tig == 0) {
                int r0 = oBase + warp_m*32 + mt*16 + gid;
                atomicAdd(&Psum[r0*24 + cg], a * invN);
                atomicAdd(&Psum[(r0 + 8)*24 + cg], b2 * invN);
            }
        }
    }
}

// ---------------- 5. VN leaky-relu: x from pairs (or P), d from fp32; out pairs --------
// Optionally zeroes Pzero[0..H3*24) (for the fused pool of the NEXT gemm).
__global__ void lrelu_kernel(const bf16* __restrict__ Xh, const bf16* __restrict__ Xl,
                             const float* __restrict__ P, const float* __restrict__ Dsrc,
                             bf16* __restrict__ Dh, bf16* __restrict__ Dl,
                             float* __restrict__ Pzero) {
    int idx = blockIdx.x * 256 + threadIdx.x;
    if (Pzero && idx < H3*24) Pzero[idx] = 0.f;
    int c = idx >> 13;
    int r = idx & 8191;
    int b = r >> 10, n = r & 1023;
    size_t base = (size_t)c*M_ + (size_t)b*3*N_ + n;
    float x0, x1, x2;
    if (P != nullptr && c >= H3) {
        int pc = (c - H3)*24 + b*3;
        x0 = P[pc]; x1 = P[pc + 1]; x2 = P[pc + 2];
    } else {
        x0 = __bfloat162float(Xh[base])        + __bfloat162float(Xl[base]);
        x1 = __bfloat162float(Xh[base + N_])   + __bfloat162float(Xl[base + N_]);
        x2 = __bfloat162float(Xh[base + 2*N_]) + __bfloat162float(Xl[base + 2*N_]);
    }
    float d0 = Dsrc[base], d1 = Dsrc[base + N_], d2 = Dsrc[base + 2*N_];
    float o0 = x0, o1 = x1, o2 = x2;
    float dot = x0*d0 + x1*d1 + x2*d2;
    if (dot < 0.f) {
        float dd = d0*d0 + d1*d1 + d2*d2;
        float s = dot / (dd + EPSF);
        o0 = x0 - s*d0; o1 = x1 - s*d1; o2 = x2 - s*d2;
    }
    bf16 h, l;
    split_bf(o0, h, l); Dh[base]        = h; Dl[base]        = l;
    split_bf(o1, h, l); Dh[base + N_]   = h; Dl[base + N_]   = l;
    split_bf(o2, h, l); Dh[base + 2*N_] = h; Dl[base + 2*N_] = l;
}

// ---------------- 7. head ----------------
__global__ void final_kernel(const float* __restrict__ Wd, const float* __restrict__ Wc,
                             float* __restrict__ out) {
    __shared__ float s_net[H3*24];
    __shared__ float s_act[H3*24];
    int o = threadIdx.x;
    for (int t = o; t < H3*24; t += 128) s_net[t] = g_P[t];
    __syncthreads();

    float dcol[24];
#pragma unroll
    for (int col = 0; col < 24; col++) dcol[col] = 0.f;
    for (int i = 0; i < H3; i++) {
        float w = Wd[o*H3 + i];
#pragma unroll
        for (int col = 0; col < 24; col++) dcol[col] += w * s_net[i*24 + col];
    }
#pragma unroll
    for (int b = 0; b < 8; b++) {
        float x0 = s_net[o*24 + b*3], x1 = s_net[o*24 + b*3 + 1], x2 = s_net[o*24 + b*3 + 2];
        float d0 = dcol[b*3], d1 = dcol[b*3 + 1], d2 = dcol[b*3 + 2];
        float dot = x0*d0 + x1*d1 + x2*d2;
        float a0 = x0, a1 = x1, a2 = x2;
        if (dot < 0.f) {
            float dd = d0*d0 + d1*d1 + d2*d2;
            float s = dot / (dd + EPSF);
            a0 = x0 - s*d0; a1 = x1 - s*d1; a2 = x2 - s*d2;
        }
        s_act[o*24 + b*3] = a0; s_act[o*24 + b*3 + 1] = a1; s_act[o*24 + b*3 + 2] = a2;
    }
    __syncthreads();

    float oc[24];
#pragma unroll
    for (int col = 0; col < 24; col++) oc[col] = 0.f;
    for (int i = 0; i < H3; i++) {
        float w = Wc[o*H3 + i];
#pragma unroll
        for (int col = 0; col < 24; col++) oc[col] += w * s_act[i*24 + col];
    }
#pragma unroll
    for (int col = 0; col < 24; col++) {
        int b = col / 3, v = col % 3;
        out[b*384 + o*3 + v] = oc[col];
    }
}

// ---------------- host ----------------
static float* symaddrf(const void* sym) {
    void* p = nullptr; cudaGetSymbolAddress(&p, sym); return (float*)p;
}
static bf16* symaddrb(const void* sym) {
    void* p = nullptr; cudaGetSymbolAddress(&p, sym); return (bf16*)p;
}

extern "C" void kernel_launch(void* const* d_in, const int* in_sizes, int n_in,
                              void* d_out, int out_size) {
    const float* p      = (const float*)d_in[0];
    const float* Wpos   = (const float*)d_in[1];
    const float* Wd0s   = (const float*)d_in[2];
    const float* W0s    = (const float*)d_in[3];
    const float* Wd1s   = (const float*)d_in[4];
    const float* W1s    = (const float*)d_in[5];
    const float* Wss    = (const float*)d_in[6];
    const float* Wd_act = (const float*)d_in[7];
    const float* Wc     = (const float*)d_in[8];
    float* out = (float*)d_out;

    float* DS    = symaddrf(g_DS);
    float* S     = DS + (size_t)C2*M_;
    float* D1    = symaddrf(g_D1);
    float* Wcat  = symaddrf(g_Wcat);
    float* Badd  = symaddrf(g_Badd);
    float* P     = symaddrf(g_P);
    bf16 *X0h = symaddrb(g_X0h), *X0l = symaddrb(g_X0l);
    bf16 *DSh = symaddrb(g_DSh), *DSl = symaddrb(g_DSl);
    bf16 *Nth = symaddrb(g_Nth), *Ntl = symaddrb(g_Ntl);
    bf16 *D1h = symaddrb(g_D1h), *D1l = symaddrb(g_D1l);
    bf16 *WcH = symaddrb(g_WcatH), *WcL = symaddrb(g_WcatL);
    bf16 *W0H = symaddrb(g_W0H),   *W0L = symaddrb(g_W0L);
    bf16 *Wd1H = symaddrb(g_Wd1H), *Wd1L = symaddrb(g_Wd1L);
    bf16 *W1H = symaddrb(g_W1H),   *W1L = symaddrb(g_W1L);

    center_kernel<<<B_, 256>>>(p);
    knn_mean_kernel<<<B_*4, 256>>>();
    featpos_kernel<<<B_*3*8, 256>>>(Wpos);
    wsplit_kernel<<<(5*384*C2)/256, 256>>>(Wd0s, Wss);
    splitall_kernel<<<(5*H3*C2 + 2*5*H3*H3)/256, 256>>>(W0s, Wd1s, W1s);

    for (int i = 0; i < 5; i++) {
        size_t oc2 = (size_t)i*384*C2;
        const bf16* WciH = WcH + oc2; const bf16* WciL = WcL + oc2;
        const bf16* W0iH = W0H + (size_t)i*H3*C2;  const bf16* W0iL = W0L + (size_t)i*H3*C2;
        const bf16* Wd1iH = Wd1H + (size_t)i*H3*H3; const bf16* Wd1iL = Wd1L + (size_t)i*H3*H3;
        const bf16* W1iH = W1H + (size_t)i*H3*H3;  const bf16* W1iL = W1L + (size_t)i*H3*H3;

        if (i == 0) {
            gemm_bfx3_kernel<<<dim3(384, 3), 256>>>(WciH, WciL, C2, X0h, X0l,
                DS, nullptr, nullptr, C2, nullptr, nullptr, nullptr);
        } else {
            badd_kernel<<<36, 256>>>(Wcat + oc2);
            gemm_bfx3_kernel<<<dim3(384, 3), 256>>>(WciH, WciL, C2, X0h, X0l,
                DS, nullptr, nullptr, H3, Badd, nullptr, nullptr);
        }
        // D' = lrelu(X, D) -> pairs (256 ch; for i>0 channels 128..255 x comes from P)
        lrelu_kernel<<<(C2*8192)/256, 256>>>(X0h, X0l, (i == 0) ? nullptr : P, DS,
                                             DSh, DSl, nullptr);
        // Nt = W0 @ D'  (K=256) -> pairs
        gemm_bfx3_kernel<<<dim3(384, 1), 256>>>(W0iH, W0iL, C2, DSh, DSl,
            nullptr, Nth, Ntl, C2, nullptr, nullptr, nullptr);
        // D1 = Wd1 @ Nt (K=128) -> fp32
        gemm_bfx3_kernel<<<dim3(384, 1), 256>>>(Wd1iH, Wd1iL, H3, Nth, Ntl,
            D1, nullptr, nullptr, H3, nullptr, nullptr, nullptr);
        // D1' = lrelu(Nt, D1) -> pairs (128 ch); zeroes P for the fused pool below
        lrelu_kernel<<<(H3*8192)/256, 256>>>(Nth, Ntl, nullptr, D1, D1h, D1l, P);
        // netX = W1 @ D1' + S (K=128) -> pairs into X0; fused pool accumulates P
        gemm_bfx3_kernel<<<dim3(384, 1), 256>>>(W1iH, W1iL, H3, D1h, D1l,
            nullptr, X0h, X0l, H3, nullptr, S, P);
    }

    final_kernel<<<1, 128>>>(Wd_act, Wc, out);
}